// round 13
// baseline (speedup 1.0000x reference)
#include <cuda_runtime.h>
#include <math.h>

// Problem dims
#define NXc 128
#define NYc 64
#define NMc 32
#define NDTc 32
#define NUc 32
#define NDc 32
#define NSTEPSc 1024
#define Bc 128
#define TPc 64

// Output offsets (floats) for the flattened 11-tuple
#define OFF_X      ((size_t)0)
#define OFF_Y      ((size_t)16777216)
#define OFF_U      ((size_t)25165824)
#define OFF_SXMIN  ((size_t)29360128)
#define OFF_SXMAX  ((size_t)46137344)
#define OFF_SUMIN  ((size_t)62914560)
#define OFF_SUMAX  ((size_t)67108864)
#define OFF_SDXX   ((size_t)71303168)
#define OFF_SDXU   ((size_t)88080384)
#define OFF_SDXD   ((size_t)104857600)
#define OFF_SPECT  ((size_t)121634816)

// ---------------- module-scope scratch ----------------
__device__ float g_WA[NXc * NXc];
__device__ float g_WA2[NXc * NXc];               // WA @ WA
__device__ float g_WC[NXc * NYc];
__device__ float g_WE[NDc * NXc];
__device__ float g_WB[NUc * NXc];
__device__ float g_bvec[NXc];
__device__ float g_x0[Bc * NXc];
__device__ float g_C[(size_t)NSTEPSc * Bc * NXc];        // 64 MB
__device__ float g_C2[(size_t)(NSTEPSc / 2) * Bc * NXc]; // 32 MB
__device__ float g_accP[128 * 8];                        // per-block Gram partials

__device__ __forceinline__ float sigmoid_f(float x) { return 1.0f / (1.0f + expf(-x)); }
__device__ __forceinline__ float relu_f(float x) { return fmaxf(x, 0.0f); }
__device__ __forceinline__ float gelu_tanh(float x) {
    float x3 = x * x * x;
    float t = tanhf(0.7978845608028654f * (x + 0.044715f * x3));
    return 0.5f * x * (1.0f + t);
}

// ---------------- kernel 1: spectral weights + Gram partials -----------------
__global__ void __launch_bounds__(128) k_setup(
    const float* __restrict__ UA, const float* __restrict__ sigA, const float* __restrict__ VA,
    const float* __restrict__ UC, const float* __restrict__ sigC, const float* __restrict__ VC)
{
    __shared__ float sA[128], sC[64], rowUA[128], rowUC[64];
    __shared__ float colUA[128], colVA[128], colUC[128], colVC[64];
    __shared__ float red[4];
    int i = blockIdx.x, j = threadIdx.x;

    sA[j] = 0.1f + 0.8f * sigmoid_f(sigA[j]);
    rowUA[j] = UA[i * 128 + j];
    colUA[j] = UA[j * 128 + i];
    colVA[j] = VA[j * 128 + i];
    colUC[j] = UC[j * 128 + i];
    if (j < 64) {
        sC[j] = 0.9f + 0.1f * sigmoid_f(sigC[j]);
        rowUC[j] = UC[i * 128 + j];
        if (i < 64) colVC[j] = VC[j * 64 + i];
    }
    __syncthreads();

    float acc = 0.0f;
    #pragma unroll 8
    for (int k = 0; k < 128; k++) acc = fmaf(rowUA[k] * sA[k], VA[k * 128 + j], acc);
    g_WA[i * 128 + j] = acc;

    if (j < 64) {
        float a = 0.0f;
        #pragma unroll 8
        for (int k = 0; k < 64; k++) a = fmaf(rowUC[k] * sC[k], VC[k * 64 + j], a);
        g_WC[i * 64 + j] = a;
    }

    float gua = 0.0f, gva = 0.0f, guc = 0.0f;
    #pragma unroll 8
    for (int k = 0; k < 128; k++) {
        gua = fmaf(colUA[k], UA[k * 128 + j], gua);
        gva = fmaf(colVA[k], VA[k * 128 + j], gva);
        guc = fmaf(colUC[k], UC[k * 128 + j], guc);
    }
    float p6 = 0.0f, p7 = 0.0f;
    if (i < 64 && j < 64) {
        float g = 0.0f;
        #pragma unroll 8
        for (int k = 0; k < 64; k++) g = fmaf(colVC[k], VC[k * 64 + j], g);
        p6 = g * g;
        float v = VC[i * 64 + j];
        p7 = v * v;
    }
    float part[8];
    part[0] = gua * gua;
    part[1] = rowUA[j] * rowUA[j];
    part[2] = gva * gva;
    { float v = VA[i * 128 + j]; part[3] = v * v; }
    part[4] = guc * guc;
    { float v = UC[i * 128 + j]; part[5] = v * v; }
    part[6] = p6;
    part[7] = p7;

    for (int v = 0; v < 8; v++) {
        float x = part[v];
        #pragma unroll
        for (int o = 16; o; o >>= 1) x += __shfl_xor_sync(0xffffffffu, x, o);
        if ((j & 31) == 0) red[j >> 5] = x;
        __syncthreads();
        if (j == 0) g_accP[i * 8 + v] = red[0] + red[1] + red[2] + red[3];
        __syncthreads();
    }
}

// ---------------- kernel 2: W_E, W_B, bvec, SpectErr -------------------------
__global__ void __launch_bounds__(128) k_setup2(
    const float* __restrict__ x0c, const float* __restrict__ wE,
    const float* __restrict__ sE, const float* __restrict__ wB,
    float* __restrict__ out)
{
    __shared__ float xc[128];
    __shared__ float acc8[8];
    int j = threadIdx.x;
    xc[j] = x0c[j];
    if (j < 8) {
        float s = 0.0f;
        for (int i = 0; i < 128; i++) s += g_accP[i * 8 + j];
        acc8[j] = s;
    }
    __syncthreads();

    float b = 0.0f;
    #pragma unroll 8
    for (int k = 0; k < 128; k++) b = fmaf(xc[k], g_WA[k * 128 + j], b);
    g_bvec[j] = b;

    float mx = -1e30f;
    for (int i = 0; i < 32; i++) mx = fmaxf(mx, wE[i * 128 + j]);
    float s = 0.0f;
    for (int i = 0; i < 32; i++) s += expf(wE[i * 128 + j] - mx);
    float inv = 1.0f / s;
    for (int i = 0; i < 32; i++) {
        float sm = expf(wE[i * 128 + j] - mx) * inv;
        float sc = 1.0f - 0.95f * sigmoid_f(sE[i * 128 + j]);
        g_WE[i * 128 + j] = sc * sm;
    }
    for (int idx = j; idx < NUc * NXc; idx += 128) g_WB[idx] = relu_f(wB[idx]);

    float errA = (acc8[0] - 2.0f * acc8[1] + 128.0f) * (1.0f / 16384.0f)
               + (acc8[2] - 2.0f * acc8[3] + 128.0f) * (1.0f / 16384.0f);
    float errC = (acc8[4] - 2.0f * acc8[5] + 128.0f) * (1.0f / 16384.0f)
               + (acc8[6] - 2.0f * acc8[7] + 64.0f) * (1.0f / 4096.0f);
    float sp = errA + errC;
    for (int idx = j; idx < NSTEPSc; idx += 128) out[OFF_SPECT + idx] = sp;
}

// ---------------- kernel: WA2 = WA @ WA --------------------------------------
__global__ void __launch_bounds__(128) k_wa2() {
    __shared__ float rowA[128];
    int i = blockIdx.x, j = threadIdx.x;
    rowA[j] = g_WA[i * 128 + j];
    __syncthreads();
    float acc = 0.0f;
    #pragma unroll 8
    for (int k = 0; k < 128; k++) acc = fmaf(rowA[k], g_WA[k * 128 + j], acc);
    g_WA2[i * 128 + j] = acc;
}

// ---------------- kernel 3: RNN warmup (proven version) ----------------------
__global__ void __launch_bounds__(512) k_rnn(
    const float* __restrict__ Ym, const float* __restrict__ Wih,
    const float* __restrict__ Whh)
{
    __shared__ float h_sh[128];
    __shared__ float ym_sh[2][64];
    __shared__ float p_sh[3 * 128];
    int tid = threadIdx.x;
    int b = blockIdx.x;
    int j = tid & 127, h = tid >> 7;

    float whh_r[32];
    #pragma unroll
    for (int kk = 0; kk < 32; kk++) whh_r[kk] = Whh[(h * 32 + kk) * 128 + j];
    float wih_r[16];
    #pragma unroll
    for (int kk = 0; kk < 16; kk++) wih_r[kk] = Wih[(h * 16 + kk) * 128 + j];

    if (tid < 128) h_sh[tid] = 0.0f;
    if (tid >= 448) ym_sh[0][tid - 448] = Ym[(size_t)b * 64 + (tid - 448)];
    __syncthreads();

    for (int t = 0; t < TPc; t++) {
        const float* yc = ym_sh[t & 1];
        float acc = 0.0f;
        #pragma unroll
        for (int kk = 0; kk < 16; kk++)
            acc = fmaf(yc[h * 16 + kk], wih_r[kk], acc);
        #pragma unroll
        for (int kk = 0; kk < 32; kk++)
            acc = fmaf(h_sh[h * 32 + kk], whh_r[kk], acc);

        if (tid >= 448 && t + 1 < TPc)
            ym_sh[(t + 1) & 1][tid - 448] = Ym[((size_t)(t + 1) * Bc + b) * 64 + (tid - 448)];

        if (h) p_sh[(h - 1) * 128 + j] = acc;
        __syncthreads();
        if (h == 0)
            h_sh[j] = gelu_tanh(acc + p_sh[j] + p_sh[128 + j] + p_sh[256 + j]);
        __syncthreads();
    }
    if (tid < 128) g_x0[b * 128 + tid] = h_sh[tid];
}

// ---------------- kernel 4: precompute, 4-sample batched (R8/R9 proven) ------
#define SM_PRE_FLOATS (4096*3 + 4096*2 + 256 + 128*3)
__global__ void __launch_bounds__(512) k_pre(
    const float* __restrict__ M, const float* __restrict__ DTin,
    const float* __restrict__ Din, const float* __restrict__ UMIN,
    const float* __restrict__ UMAX, const float* __restrict__ Whf,
    const float* __restrict__ dxmn_g, const float* __restrict__ dxmx_g,
    float* __restrict__ out)
{
    extern __shared__ float sm[];
    float* m_all   = sm;             // 4096
    float* dt_all  = sm + 4096;      // 4096
    float* d_all   = sm + 8192;      // 4096
    float* wb_sh   = sm + 12288;     // 4096
    float* we_sh   = sm + 16384;     // 4096
    float* u_sh    = sm + 20480;     // 2 x 128
    float* bvec_sh = sm + 20736;     // 128
    float* dxmn_sh = sm + 20864;     // 128
    float* dxmx_sh = sm + 20992;     // 128

    int tid = threadIdx.x;
    int t = blockIdx.x;
    int o = tid >> 4, l = tid & 15;
    int lh = l >> 3, lj = l & 7;

    float4 w[16];
    const float4* whf4 = (const float4*)Whf;
    #pragma unroll
    for (int i = 0; i < 16; i++)
        w[i] = whf4[(o * 32 + lh * 16 + i) * 8 + lj];

    size_t tb = (size_t)t * 4096;
    {
        const float4* M4  = (const float4*)(M + tb);
        const float4* DT4 = (const float4*)(DTin + tb);
        const float4* D4  = (const float4*)(Din + tb);
        float4* m4  = (float4*)m_all;
        float4* dt4 = (float4*)dt_all;
        float4* d4  = (float4*)d_all;
        #pragma unroll
        for (int idx = tid; idx < 1024; idx += 512) {
            m4[idx] = M4[idx];
            dt4[idx] = DT4[idx];
            d4[idx] = D4[idx];
        }
    }
    for (int idx = tid; idx < 4096; idx += 512) {
        wb_sh[idx] = g_WB[idx];
        we_sh[idx] = g_WE[idx];
    }
    if (tid < 128) {
        bvec_sh[tid] = g_bvec[tid];
        dxmn_sh[tid] = dxmn_g[tid];
        dxmx_sh[tid] = dxmx_g[tid];
    }
    int uo = tid - 384;
    float umn_c[4], umx_c[4], umn_n[4], umx_n[4];
    __syncthreads();

    for (int grp = 0; grp <= 32; grp++) {
        int cur = grp & 1;

        if (uo >= 0 && uo < 32 && grp < 32) {
            #pragma unroll
            for (int s = 0; s < 4; s++) {
                size_t idx = tb + (size_t)(grp * 4 + s) * 32 + uo;
                umn_n[s] = UMIN[idx];
                umx_n[s] = UMAX[idx];
            }
        }

        // ---- S1: factorized bilinear for samples grp*4 .. grp*4+3
        if (grp < 32) {
            int b0 = grp * 4;
            float4 dtv[4];
            #pragma unroll
            for (int s = 0; s < 4; s++)
                dtv[s] = ((const float4*)(dt_all + (b0 + s) * 32))[lj];
            float acc[4] = {0.f, 0.f, 0.f, 0.f};
            #pragma unroll
            for (int i4 = 0; i4 < 4; i4++) {
                float4 mv[4];
                #pragma unroll
                for (int s = 0; s < 4; s++)
                    mv[s] = ((const float4*)(m_all + (b0 + s) * 32 + lh * 16))[i4];
                #pragma unroll
                for (int s = 0; s < 4; s++) {
                    int i = i4 * 4;
                    float p0 = w[i].x * dtv[s].x;
                    p0 = fmaf(w[i].y, dtv[s].y, p0);
                    p0 = fmaf(w[i].z, dtv[s].z, p0);
                    p0 = fmaf(w[i].w, dtv[s].w, p0);
                    acc[s] = fmaf(mv[s].x, p0, acc[s]);
                    float p1 = w[i + 1].x * dtv[s].x;
                    p1 = fmaf(w[i + 1].y, dtv[s].y, p1);
                    p1 = fmaf(w[i + 1].z, dtv[s].z, p1);
                    p1 = fmaf(w[i + 1].w, dtv[s].w, p1);
                    acc[s] = fmaf(mv[s].y, p1, acc[s]);
                    float p2 = w[i + 2].x * dtv[s].x;
                    p2 = fmaf(w[i + 2].y, dtv[s].y, p2);
                    p2 = fmaf(w[i + 2].z, dtv[s].z, p2);
                    p2 = fmaf(w[i + 2].w, dtv[s].w, p2);
                    acc[s] = fmaf(mv[s].z, p2, acc[s]);
                    float p3 = w[i + 3].x * dtv[s].x;
                    p3 = fmaf(w[i + 3].y, dtv[s].y, p3);
                    p3 = fmaf(w[i + 3].z, dtv[s].z, p3);
                    p3 = fmaf(w[i + 3].w, dtv[s].w, p3);
                    acc[s] = fmaf(mv[s].w, p3, acc[s]);
                }
            }
            #pragma unroll
            for (int s = 0; s < 4; s++) {
                float a = acc[s];
                a += __shfl_xor_sync(0xffffffffu, a, 1);
                a += __shfl_xor_sync(0xffffffffu, a, 2);
                a += __shfl_xor_sync(0xffffffffu, a, 4);
                a += __shfl_xor_sync(0xffffffffu, a, 8);
                if (l == 0) u_sh[cur * 128 + s * 32 + o] = a;
            }
        }

        // ---- S2: drain group grp-1
        if (grp >= 1) {
            int gb = (grp - 1) * 4;
            int pv = (grp - 1) & 1;
            if (tid < 128) {
                float bu[4] = {0.f, 0.f, 0.f, 0.f};
                float ed[4] = {0.f, 0.f, 0.f, 0.f};
                #pragma unroll
                for (int oo = 0; oo < 32; oo++) {
                    float wbv = wb_sh[oo * 128 + tid];
                    float wev = we_sh[oo * 128 + tid];
                    #pragma unroll
                    for (int s = 0; s < 4; s++) {
                        bu[s] = fmaf(u_sh[pv * 128 + s * 32 + oo], wbv, bu[s]);
                        ed[s] = fmaf(d_all[(gb + s) * 32 + oo], wev, ed[s]);
                    }
                }
                float dn = dxmn_sh[tid], dx = dxmx_sh[tid];
                float bv = bvec_sh[tid];
                #pragma unroll
                for (int s = 0; s < 4; s++) {
                    size_t base128 = ((size_t)t * Bc + (gb + s)) * 128;
                    out[OFF_SDXU + base128 + tid] = relu_f(dn - bu[s]) + relu_f(bu[s] - dx);
                    out[OFF_SDXD + base128 + tid] = relu_f(dn - ed[s]) + relu_f(ed[s] - dx);
                    g_C[base128 + tid] = bu[s] + ed[s] + bv;
                }
            } else if (uo >= 0 && uo < 32) {
                #pragma unroll
                for (int s = 0; s < 4; s++) {
                    float uu = u_sh[pv * 128 + s * 32 + uo];
                    size_t base32 = tb + (size_t)(gb + s) * 32;
                    out[OFF_U + base32 + uo]     = uu;
                    out[OFF_SUMIN + base32 + uo] = relu_f(umn_c[s] - uu);
                    out[OFF_SUMAX + base32 + uo] = relu_f(uu - umx_c[s]);
                }
            }
        }
        if (uo >= 0 && uo < 32) {
            #pragma unroll
            for (int s = 0; s < 4; s++) { umn_c[s] = umn_n[s]; umx_c[s] = umx_n[s]; }
        }
        __syncthreads();
    }
}

// ---------------- kernel: C2 = Ceven @ WA + Codd  (register-tiled GEMM) ------
#define SM_C2_BYTES ((64*128 + 128*128) * 4)
__global__ void __launch_bounds__(256) k_c2(const float* __restrict__ Cg)
{
    extern __shared__ float smc[];
    float* Xs = smc;            // 64 x 128
    float* Ws = smc + 8192;     // 128 x 128
    int tid = threadIdx.x;
    int p = blockIdx.x >> 1;
    int half = blockIdx.x & 1;

    {
        const float4* wsrc = (const float4*)g_WA;
        float4* wdst = (float4*)Ws;
        #pragma unroll
        for (int i = 0; i < 16; i++) wdst[tid + i * 256] = wsrc[tid + i * 256];
        const float4* xsrc = (const float4*)(Cg + ((size_t)(2 * p) * Bc + half * 64) * 128);
        float4* xdst = (float4*)Xs;
        #pragma unroll
        for (int i = 0; i < 8; i++) xdst[tid + i * 256] = xsrc[tid + i * 256];
    }
    __syncthreads();

    int rg = tid >> 4;
    int cg = tid & 15;
    float acc[4][8];
    #pragma unroll
    for (int i = 0; i < 4; i++)
        #pragma unroll
        for (int c = 0; c < 8; c++) acc[i][c] = 0.0f;

    const float4* Xf4 = (const float4*)Xs;
    const float4* Wf4 = (const float4*)Ws;
    #pragma unroll 8
    for (int k4 = 0; k4 < 32; k4++) {
        float4 wv[4][2];
        #pragma unroll
        for (int kk = 0; kk < 4; kk++) {
            wv[kk][0] = Wf4[(k4 * 4 + kk) * 32 + cg * 2];
            wv[kk][1] = Wf4[(k4 * 4 + kk) * 32 + cg * 2 + 1];
        }
        #pragma unroll
        for (int i = 0; i < 4; i++) {
            float4 xv = Xf4[(rg * 4 + i) * 32 + k4];
            #pragma unroll
            for (int hc = 0; hc < 2; hc++) {
                acc[i][hc * 4 + 0] = fmaf(xv.x, wv[0][hc].x, acc[i][hc * 4 + 0]);
                acc[i][hc * 4 + 1] = fmaf(xv.x, wv[0][hc].y, acc[i][hc * 4 + 1]);
                acc[i][hc * 4 + 2] = fmaf(xv.x, wv[0][hc].z, acc[i][hc * 4 + 2]);
                acc[i][hc * 4 + 3] = fmaf(xv.x, wv[0][hc].w, acc[i][hc * 4 + 3]);
                acc[i][hc * 4 + 0] = fmaf(xv.y, wv[1][hc].x, acc[i][hc * 4 + 0]);
                acc[i][hc * 4 + 1] = fmaf(xv.y, wv[1][hc].y, acc[i][hc * 4 + 1]);
                acc[i][hc * 4 + 2] = fmaf(xv.y, wv[1][hc].z, acc[i][hc * 4 + 2]);
                acc[i][hc * 4 + 3] = fmaf(xv.y, wv[1][hc].w, acc[i][hc * 4 + 3]);
                acc[i][hc * 4 + 0] = fmaf(xv.z, wv[2][hc].x, acc[i][hc * 4 + 0]);
                acc[i][hc * 4 + 1] = fmaf(xv.z, wv[2][hc].y, acc[i][hc * 4 + 1]);
                acc[i][hc * 4 + 2] = fmaf(xv.z, wv[2][hc].z, acc[i][hc * 4 + 2]);
                acc[i][hc * 4 + 3] = fmaf(xv.z, wv[2][hc].w, acc[i][hc * 4 + 3]);
                acc[i][hc * 4 + 0] = fmaf(xv.w, wv[3][hc].x, acc[i][hc * 4 + 0]);
                acc[i][hc * 4 + 1] = fmaf(xv.w, wv[3][hc].y, acc[i][hc * 4 + 1]);
                acc[i][hc * 4 + 2] = fmaf(xv.w, wv[3][hc].z, acc[i][hc * 4 + 2]);
                acc[i][hc * 4 + 3] = fmaf(xv.w, wv[3][hc].w, acc[i][hc * 4 + 3]);
            }
        }
    }

    const float* codd = Cg + ((size_t)(2 * p + 1) * Bc + half * 64) * 128;
    float* o = g_C2 + ((size_t)p * Bc + half * 64) * 128;
    #pragma unroll
    for (int i = 0; i < 4; i++) {
        int row = rg * 4 + i;
        const float4* co = (const float4*)(codd + row * 128) + cg * 2;
        float4* od = (float4*)(o + row * 128) + cg * 2;
        float4 c0 = co[0], c1 = co[1];
        od[0] = make_float4(acc[i][0] + c0.x, acc[i][1] + c0.y,
                            acc[i][2] + c0.z, acc[i][3] + c0.w);
        od[1] = make_float4(acc[i][4] + c1.x, acc[i][5] + c1.y,
                            acc[i][6] + c1.z, acc[i][7] + c1.w);
    }
}

// ---------------- kernel 5: sequential rollout (slim: X only) ----------------
// R10 core, but ONLY computes/stores X; all slack outputs moved to k_slack.
__global__ void __launch_bounds__(256) k_seq(
    const float* __restrict__ Cg, float* __restrict__ out)
{
    __shared__ float xbuf[2][128];
    int tid = threadIdx.x;
    int b = blockIdx.x;
    int j = tid >> 1, h = tid & 1;

    float wa[64], wa2[64];
    #pragma unroll
    for (int kk = 0; kk < 64; kk++) {
        wa[kk]  = g_WA [(h * 64 + kk) * 128 + j];
        wa2[kk] = g_WA2[(h * 64 + kk) * 128 + j];
    }

    if (h == 0) xbuf[0][j] = g_x0[b * 128 + j];

    float cA[2];
    #pragma unroll
    for (int pp = 0; pp < 2; pp++) {
        cA[pp] = h ? g_C2[((size_t)pp * Bc + b) * 128 + j]
                   : Cg[((size_t)(2 * pp) * Bc + b) * 128 + j];
    }
    __syncthreads();

    for (int p = 0; p < NSTEPSc / 2; p++) {
        int cur = p & 1;
        const float4* x4 = ((const float4*)xbuf[cur]) + h * 16;
        float p1a = 0.f, p1b = 0.f, p2a = 0.f, p2b = 0.f;
        #pragma unroll
        for (int kk = 0; kk < 16; kk++) {
            float4 xv = x4[kk];
            p1a = fmaf(xv.x, wa[kk * 4 + 0], p1a);
            p1b = fmaf(xv.y, wa[kk * 4 + 1], p1b);
            p1a = fmaf(xv.z, wa[kk * 4 + 2], p1a);
            p1b = fmaf(xv.w, wa[kk * 4 + 3], p1b);
            p2a = fmaf(xv.x, wa2[kk * 4 + 0], p2a);
            p2b = fmaf(xv.y, wa2[kk * 4 + 1], p2b);
            p2a = fmaf(xv.z, wa2[kk * 4 + 2], p2a);
            p2b = fmaf(xv.w, wa2[kk * 4 + 3], p2b);
        }
        float y1p = p1a + p1b, y2p = p2a + p2b;
        float y1o = __shfl_xor_sync(0xffffffffu, y1p, 1);
        float y2o = __shfl_xor_sync(0xffffffffu, y2p, 1);
        float cmine = cA[cur];
        float coth  = __shfl_xor_sync(0xffffffffu, cmine, 1);
        float ct = h ? coth : cmine;
        float c2 = h ? cmine : coth;
        float y1 = y1p + y1o + ct;
        float y2 = y2p + y2o + c2;

        int ts = 2 * p + h;
        out[OFF_X + ((size_t)ts * Bc + b) * 128 + j] = h ? y2 : y1;
        if (h == 0) xbuf[1 - cur][j] = y2;

        if (p + 2 < NSTEPSc / 2) {
            cA[cur] = h ? g_C2[((size_t)(p + 2) * Bc + b) * 128 + j]
                        : Cg[((size_t)(2 * (p + 2)) * Bc + b) * 128 + j];
        }
        __syncthreads();
    }
}

// ---------------- kernel: slack post-pass (SXMIN/SXMAX/SDXX) -----------------
// Fully parallel float4 streaming: SDXX[t] = X[t] - X[t-1] (X[-1] = x0).
// 2048 blocks x 256 threads x 8 float4.
__global__ void __launch_bounds__(256) k_slack(
    const float* __restrict__ XMIN, const float* __restrict__ XMAX,
    float* __restrict__ out)
{
    size_t base = ((size_t)blockIdx.x * 256 + threadIdx.x) * 8;  // float4 index
    const float4* X4   = (const float4*)(out + OFF_X);
    const float4* MN4  = (const float4*)XMIN;
    const float4* MX4  = (const float4*)XMAX;
    const float4* X04  = (const float4*)g_x0;
    float4* SMN4 = (float4*)(out + OFF_SXMIN);
    float4* SMX4 = (float4*)(out + OFF_SXMAX);
    float4* SDX4 = (float4*)(out + OFF_SDXX);

    #pragma unroll
    for (int i = 0; i < 8; i++) {
        size_t f = base + i;                 // global float4 idx; 4096 per step
        float4 x  = X4[f];
        float4 mn = MN4[f];
        float4 mx = MX4[f];
        float4 xp = (f < 4096) ? X04[f] : X4[f - 4096];
        SMN4[f] = make_float4(relu_f(mn.x - x.x), relu_f(mn.y - x.y),
                              relu_f(mn.z - x.z), relu_f(mn.w - x.w));
        SMX4[f] = make_float4(relu_f(x.x - mx.x), relu_f(x.y - mx.y),
                              relu_f(x.z - mx.z), relu_f(x.w - mx.w));
        SDX4[f] = make_float4(x.x - xp.x, x.y - xp.y, x.z - xp.z, x.w - xp.w);
    }
}

// ---------------- kernel 6: Y = X @ W_C (register-tiled GEMM) ----------------
#define SM_POST_BYTES ((64*128 + 128*64) * 4)
__global__ void __launch_bounds__(256) k_post(float* __restrict__ out)
{
    extern __shared__ float smp[];
    float* Xs = smp;            // 64 x 128
    float* Ws = smp + 8192;     // 128 x 64
    int tid = threadIdx.x;
    size_t row0 = (size_t)blockIdx.x * 64;

    {
        const float4* wsrc = (const float4*)g_WC;
        float4* wdst = (float4*)Ws;
        #pragma unroll
        for (int i = 0; i < 8; i++) wdst[tid + i * 256] = wsrc[tid + i * 256];
        const float4* xsrc = (const float4*)(out + OFF_X + row0 * 128);
        float4* xdst = (float4*)Xs;
        #pragma unroll
        for (int i = 0; i < 8; i++) xdst[tid + i * 256] = xsrc[tid + i * 256];
    }
    __syncthreads();

    int rg = tid >> 4;
    int cg = tid & 15;
    float acc[4][4];
    #pragma unroll
    for (int i = 0; i < 4; i++)
        #pragma unroll
        for (int c = 0; c < 4; c++) acc[i][c] = 0.0f;

    const float4* Xf4 = (const float4*)Xs;
    const float4* Wf4 = (const float4*)Ws;
    #pragma unroll 8
    for (int k4 = 0; k4 < 32; k4++) {
        float4 wvv[4];
        #pragma unroll
        for (int kk = 0; kk < 4; kk++)
            wvv[kk] = Wf4[(k4 * 4 + kk) * 16 + cg];
        #pragma unroll
        for (int i = 0; i < 4; i++) {
            float4 xv = Xf4[(rg * 4 + i) * 32 + k4];
            acc[i][0] = fmaf(xv.x, wvv[0].x, acc[i][0]);
            acc[i][1] = fmaf(xv.x, wvv[0].y, acc[i][1]);
            acc[i][2] = fmaf(xv.x, wvv[0].z, acc[i][2]);
            acc[i][3] = fmaf(xv.x, wvv[0].w, acc[i][3]);
            acc[i][0] = fmaf(xv.y, wvv[1].x, acc[i][0]);
            acc[i][1] = fmaf(xv.y, wvv[1].y, acc[i][1]);
            acc[i][2] = fmaf(xv.y, wvv[1].z, acc[i][2]);
            acc[i][3] = fmaf(xv.y, wvv[1].w, acc[i][3]);
            acc[i][0] = fmaf(xv.z, wvv[2].x, acc[i][0]);
            acc[i][1] = fmaf(xv.z, wvv[2].y, acc[i][1]);
            acc[i][2] = fmaf(xv.z, wvv[2].z, acc[i][2]);
            acc[i][3] = fmaf(xv.z, wvv[2].w, acc[i][3]);
            acc[i][0] = fmaf(xv.w, wvv[3].x, acc[i][0]);
            acc[i][1] = fmaf(xv.w, wvv[3].y, acc[i][1]);
            acc[i][2] = fmaf(xv.w, wvv[3].z, acc[i][2]);
            acc[i][3] = fmaf(xv.w, wvv[3].w, acc[i][3]);
        }
    }

    #pragma unroll
    for (int i = 0; i < 4; i++) {
        float4* od = (float4*)(out + OFF_Y + (row0 + rg * 4 + i) * 64) + cg;
        od[0] = make_float4(acc[i][0], acc[i][1], acc[i][2], acc[i][3]);
    }
}

// ---------------- launch ------------------------------------------------------
extern "C" void kernel_launch(void* const* d_in, const int* in_sizes, int n_in,
                              void* d_out, int out_size)
{
    const float* Ym   = (const float*)d_in[0];
    const float* M    = (const float*)d_in[1];
    const float* DTin = (const float*)d_in[2];
    const float* Din  = (const float*)d_in[3];
    const float* XMIN = (const float*)d_in[4];
    const float* XMAX = (const float*)d_in[5];
    const float* UMIN = (const float*)d_in[6];
    const float* UMAX = (const float*)d_in[7];
    const float* x0c  = (const float*)d_in[8];
    const float* UA   = (const float*)d_in[9];
    const float* sigA = (const float*)d_in[10];
    const float* VA   = (const float*)d_in[11];
    const float* UC   = (const float*)d_in[12];
    const float* sigC = (const float*)d_in[13];
    const float* VC   = (const float*)d_in[14];
    const float* wE   = (const float*)d_in[15];
    const float* sE   = (const float*)d_in[16];
    const float* wB   = (const float*)d_in[17];
    const float* Whf  = (const float*)d_in[18];
    const float* Wih  = (const float*)d_in[19];
    const float* Whh  = (const float*)d_in[20];
    const float* dxmn = (const float*)d_in[21];
    const float* dxmx = (const float*)d_in[22];
    float* out = (float*)d_out;

    static const size_t smem_pre = SM_PRE_FLOATS * sizeof(float);
    cudaFuncSetAttribute(k_pre, cudaFuncAttributeMaxDynamicSharedMemorySize,
                         (int)smem_pre);
    cudaFuncSetAttribute(k_c2, cudaFuncAttributeMaxDynamicSharedMemorySize,
                         SM_C2_BYTES);
    cudaFuncSetAttribute(k_post, cudaFuncAttributeMaxDynamicSharedMemorySize,
                         SM_POST_BYTES);

    float* Cg = nullptr;
    cudaGetSymbolAddress((void**)&Cg, g_C);

    // k_c2 stays at launch idx 3 (the profiled slot).
    k_setup<<<128, 128>>>(UA, sigA, VA, UC, sigC, VC);
    k_setup2<<<1, 128>>>(x0c, wE, sE, wB, out);
    k_pre<<<NSTEPSc, 512, smem_pre>>>(M, DTin, Din, UMIN, UMAX, Whf, dxmn, dxmx, out);
    k_c2<<<NSTEPSc, 256, SM_C2_BYTES>>>(Cg);
    k_wa2<<<128, 128>>>();
    k_rnn<<<Bc, 512>>>(Ym, Wih, Whh);
    k_seq<<<Bc, 256>>>(Cg, out);
    k_slack<<<2048, 256>>>(XMIN, XMAX, out);
    k_post<<<(NSTEPSc * Bc) / 64, 256, SM_POST_BYTES>>>(out);
}

// round 14
// speedup vs baseline: 1.1482x; 1.1482x over previous
#include <cuda_runtime.h>
#include <math.h>

// Problem dims
#define NXc 128
#define NYc 64
#define NMc 32
#define NDTc 32
#define NUc 32
#define NDc 32
#define NSTEPSc 1024
#define Bc 128
#define TPc 64
#define NSEG 8
#define SEGL 128

// Output offsets (floats) for the flattened 11-tuple
#define OFF_X      ((size_t)0)
#define OFF_Y      ((size_t)16777216)
#define OFF_U      ((size_t)25165824)
#define OFF_SXMIN  ((size_t)29360128)
#define OFF_SXMAX  ((size_t)46137344)
#define OFF_SUMIN  ((size_t)62914560)
#define OFF_SUMAX  ((size_t)67108864)
#define OFF_SDXX   ((size_t)71303168)
#define OFF_SDXU   ((size_t)88080384)
#define OFF_SDXD   ((size_t)104857600)
#define OFF_SPECT  ((size_t)121634816)

// ---------------- module-scope scratch ----------------
__device__ float g_WA[NXc * NXc];
__device__ float g_WA2[NXc * NXc];               // WA^2
__device__ float g_T1[NXc * NXc];                // power ping
__device__ float g_T2[NXc * NXc];                // power pong
__device__ float g_WA128[NXc * NXc];             // WA^128
__device__ float g_WC[NXc * NYc];
__device__ float g_WE[NDc * NXc];
__device__ float g_WB[NUc * NXc];
__device__ float g_bvec[NXc];
__device__ float g_x0[Bc * NXc];
__device__ float g_C[(size_t)NSTEPSc * Bc * NXc];        // 64 MB
__device__ float g_C2[(size_t)(NSTEPSc / 2) * Bc * NXc]; // 32 MB
__device__ float g_DL[(NSEG - 1) * Bc * NXc];            // per-seg D_L
__device__ float g_xseg[NSEG * Bc * NXc];                // x at segment starts
__device__ float g_accP[128 * 8];

__device__ __forceinline__ float sigmoid_f(float x) { return 1.0f / (1.0f + expf(-x)); }
__device__ __forceinline__ float relu_f(float x) { return fmaxf(x, 0.0f); }
__device__ __forceinline__ float gelu_tanh(float x) {
    float x3 = x * x * x;
    float t = tanhf(0.7978845608028654f * (x + 0.044715f * x3));
    return 0.5f * x * (1.0f + t);
}

// ---------------- kernel 1: spectral weights + Gram partials -----------------
__global__ void __launch_bounds__(128) k_setup(
    const float* __restrict__ UA, const float* __restrict__ sigA, const float* __restrict__ VA,
    const float* __restrict__ UC, const float* __restrict__ sigC, const float* __restrict__ VC)
{
    __shared__ float sA[128], sC[64], rowUA[128], rowUC[64];
    __shared__ float colUA[128], colVA[128], colUC[128], colVC[64];
    __shared__ float red[4];
    int i = blockIdx.x, j = threadIdx.x;

    sA[j] = 0.1f + 0.8f * sigmoid_f(sigA[j]);
    rowUA[j] = UA[i * 128 + j];
    colUA[j] = UA[j * 128 + i];
    colVA[j] = VA[j * 128 + i];
    colUC[j] = UC[j * 128 + i];
    if (j < 64) {
        sC[j] = 0.9f + 0.1f * sigmoid_f(sigC[j]);
        rowUC[j] = UC[i * 128 + j];
        if (i < 64) colVC[j] = VC[j * 64 + i];
    }
    __syncthreads();

    float acc = 0.0f;
    #pragma unroll 8
    for (int k = 0; k < 128; k++) acc = fmaf(rowUA[k] * sA[k], VA[k * 128 + j], acc);
    g_WA[i * 128 + j] = acc;

    if (j < 64) {
        float a = 0.0f;
        #pragma unroll 8
        for (int k = 0; k < 64; k++) a = fmaf(rowUC[k] * sC[k], VC[k * 64 + j], a);
        g_WC[i * 64 + j] = a;
    }

    float gua = 0.0f, gva = 0.0f, guc = 0.0f;
    #pragma unroll 8
    for (int k = 0; k < 128; k++) {
        gua = fmaf(colUA[k], UA[k * 128 + j], gua);
        gva = fmaf(colVA[k], VA[k * 128 + j], gva);
        guc = fmaf(colUC[k], UC[k * 128 + j], guc);
    }
    float p6 = 0.0f, p7 = 0.0f;
    if (i < 64 && j < 64) {
        float g = 0.0f;
        #pragma unroll 8
        for (int k = 0; k < 64; k++) g = fmaf(colVC[k], VC[k * 64 + j], g);
        p6 = g * g;
        float v = VC[i * 64 + j];
        p7 = v * v;
    }
    float part[8];
    part[0] = gua * gua;
    part[1] = rowUA[j] * rowUA[j];
    part[2] = gva * gva;
    { float v = VA[i * 128 + j]; part[3] = v * v; }
    part[4] = guc * guc;
    { float v = UC[i * 128 + j]; part[5] = v * v; }
    part[6] = p6;
    part[7] = p7;

    for (int v = 0; v < 8; v++) {
        float x = part[v];
        #pragma unroll
        for (int o = 16; o; o >>= 1) x += __shfl_xor_sync(0xffffffffu, x, o);
        if ((j & 31) == 0) red[j >> 5] = x;
        __syncthreads();
        if (j == 0) g_accP[i * 8 + v] = red[0] + red[1] + red[2] + red[3];
        __syncthreads();
    }
}

// ---------------- kernel 2: W_E, W_B, bvec, SpectErr -------------------------
__global__ void __launch_bounds__(128) k_setup2(
    const float* __restrict__ x0c, const float* __restrict__ wE,
    const float* __restrict__ sE, const float* __restrict__ wB,
    float* __restrict__ out)
{
    __shared__ float xc[128];
    __shared__ float acc8[8];
    int j = threadIdx.x;
    xc[j] = x0c[j];
    if (j < 8) {
        float s = 0.0f;
        for (int i = 0; i < 128; i++) s += g_accP[i * 8 + j];
        acc8[j] = s;
    }
    __syncthreads();

    float b = 0.0f;
    #pragma unroll 8
    for (int k = 0; k < 128; k++) b = fmaf(xc[k], g_WA[k * 128 + j], b);
    g_bvec[j] = b;

    float mx = -1e30f;
    for (int i = 0; i < 32; i++) mx = fmaxf(mx, wE[i * 128 + j]);
    float s = 0.0f;
    for (int i = 0; i < 32; i++) s += expf(wE[i * 128 + j] - mx);
    float inv = 1.0f / s;
    for (int i = 0; i < 32; i++) {
        float sm = expf(wE[i * 128 + j] - mx) * inv;
        float sc = 1.0f - 0.95f * sigmoid_f(sE[i * 128 + j]);
        g_WE[i * 128 + j] = sc * sm;
    }
    for (int idx = j; idx < NUc * NXc; idx += 128) g_WB[idx] = relu_f(wB[idx]);

    float errA = (acc8[0] - 2.0f * acc8[1] + 128.0f) * (1.0f / 16384.0f)
               + (acc8[2] - 2.0f * acc8[3] + 128.0f) * (1.0f / 16384.0f);
    float errC = (acc8[4] - 2.0f * acc8[5] + 128.0f) * (1.0f / 16384.0f)
               + (acc8[6] - 2.0f * acc8[7] + 64.0f) * (1.0f / 4096.0f);
    float sp = errA + errC;
    for (int idx = j; idx < NSTEPSc; idx += 128) out[OFF_SPECT + idx] = sp;
}

// ---------------- kernel: WA2 = WA @ WA --------------------------------------
__global__ void __launch_bounds__(128) k_wa2() {
    __shared__ float rowA[128];
    int i = blockIdx.x, j = threadIdx.x;
    rowA[j] = g_WA[i * 128 + j];
    __syncthreads();
    float acc = 0.0f;
    #pragma unroll 8
    for (int k = 0; k < 128; k++) acc = fmaf(rowA[k], g_WA[k * 128 + j], acc);
    g_WA2[i * 128 + j] = acc;
}

// ---------------- kernel: O = A @ A (matrix squaring for powers) -------------
__global__ void __launch_bounds__(128) k_matsq(
    const float* __restrict__ A, float* __restrict__ O)
{
    __shared__ float rowA[128];
    int i = blockIdx.x, j = threadIdx.x;
    rowA[j] = A[i * 128 + j];
    __syncthreads();
    float acc = 0.0f;
    #pragma unroll 8
    for (int k = 0; k < 128; k++) acc = fmaf(rowA[k], A[k * 128 + j], acc);
    O[i * 128 + j] = acc;
}

// ---------------- kernel 3: RNN warmup (proven version) ----------------------
__global__ void __launch_bounds__(512) k_rnn(
    const float* __restrict__ Ym, const float* __restrict__ Wih,
    const float* __restrict__ Whh)
{
    __shared__ float h_sh[128];
    __shared__ float ym_sh[2][64];
    __shared__ float p_sh[3 * 128];
    int tid = threadIdx.x;
    int b = blockIdx.x;
    int j = tid & 127, h = tid >> 7;

    float whh_r[32];
    #pragma unroll
    for (int kk = 0; kk < 32; kk++) whh_r[kk] = Whh[(h * 32 + kk) * 128 + j];
    float wih_r[16];
    #pragma unroll
    for (int kk = 0; kk < 16; kk++) wih_r[kk] = Wih[(h * 16 + kk) * 128 + j];

    if (tid < 128) h_sh[tid] = 0.0f;
    if (tid >= 448) ym_sh[0][tid - 448] = Ym[(size_t)b * 64 + (tid - 448)];
    __syncthreads();

    for (int t = 0; t < TPc; t++) {
        const float* yc = ym_sh[t & 1];
        float acc = 0.0f;
        #pragma unroll
        for (int kk = 0; kk < 16; kk++)
            acc = fmaf(yc[h * 16 + kk], wih_r[kk], acc);
        #pragma unroll
        for (int kk = 0; kk < 32; kk++)
            acc = fmaf(h_sh[h * 32 + kk], whh_r[kk], acc);

        if (tid >= 448 && t + 1 < TPc)
            ym_sh[(t + 1) & 1][tid - 448] = Ym[((size_t)(t + 1) * Bc + b) * 64 + (tid - 448)];

        if (h) p_sh[(h - 1) * 128 + j] = acc;
        __syncthreads();
        if (h == 0)
            h_sh[j] = gelu_tanh(acc + p_sh[j] + p_sh[128 + j] + p_sh[256 + j]);
        __syncthreads();
    }
    if (tid < 128) g_x0[b * 128 + tid] = h_sh[tid];
}

// ---------------- kernel 4: precompute, 4-sample batched (R8/R9 proven) ------
#define SM_PRE_FLOATS (4096*3 + 4096*2 + 256 + 128*3)
__global__ void __launch_bounds__(512) k_pre(
    const float* __restrict__ M, const float* __restrict__ DTin,
    const float* __restrict__ Din, const float* __restrict__ UMIN,
    const float* __restrict__ UMAX, const float* __restrict__ Whf,
    const float* __restrict__ dxmn_g, const float* __restrict__ dxmx_g,
    float* __restrict__ out)
{
    extern __shared__ float sm[];
    float* m_all   = sm;             // 4096
    float* dt_all  = sm + 4096;      // 4096
    float* d_all   = sm + 8192;      // 4096
    float* wb_sh   = sm + 12288;     // 4096
    float* we_sh   = sm + 16384;     // 4096
    float* u_sh    = sm + 20480;     // 2 x 128
    float* bvec_sh = sm + 20736;     // 128
    float* dxmn_sh = sm + 20864;     // 128
    float* dxmx_sh = sm + 20992;     // 128

    int tid = threadIdx.x;
    int t = blockIdx.x;
    int o = tid >> 4, l = tid & 15;
    int lh = l >> 3, lj = l & 7;

    float4 w[16];
    const float4* whf4 = (const float4*)Whf;
    #pragma unroll
    for (int i = 0; i < 16; i++)
        w[i] = whf4[(o * 32 + lh * 16 + i) * 8 + lj];

    size_t tb = (size_t)t * 4096;
    {
        const float4* M4  = (const float4*)(M + tb);
        const float4* DT4 = (const float4*)(DTin + tb);
        const float4* D4  = (const float4*)(Din + tb);
        float4* m4  = (float4*)m_all;
        float4* dt4 = (float4*)dt_all;
        float4* d4  = (float4*)d_all;
        #pragma unroll
        for (int idx = tid; idx < 1024; idx += 512) {
            m4[idx] = M4[idx];
            dt4[idx] = DT4[idx];
            d4[idx] = D4[idx];
        }
    }
    for (int idx = tid; idx < 4096; idx += 512) {
        wb_sh[idx] = g_WB[idx];
        we_sh[idx] = g_WE[idx];
    }
    if (tid < 128) {
        bvec_sh[tid] = g_bvec[tid];
        dxmn_sh[tid] = dxmn_g[tid];
        dxmx_sh[tid] = dxmx_g[tid];
    }
    int uo = tid - 384;
    float umn_c[4], umx_c[4], umn_n[4], umx_n[4];
    __syncthreads();

    for (int grp = 0; grp <= 32; grp++) {
        int cur = grp & 1;

        if (uo >= 0 && uo < 32 && grp < 32) {
            #pragma unroll
            for (int s = 0; s < 4; s++) {
                size_t idx = tb + (size_t)(grp * 4 + s) * 32 + uo;
                umn_n[s] = UMIN[idx];
                umx_n[s] = UMAX[idx];
            }
        }

        if (grp < 32) {
            int b0 = grp * 4;
            float4 dtv[4];
            #pragma unroll
            for (int s = 0; s < 4; s++)
                dtv[s] = ((const float4*)(dt_all + (b0 + s) * 32))[lj];
            float acc[4] = {0.f, 0.f, 0.f, 0.f};
            #pragma unroll
            for (int i4 = 0; i4 < 4; i4++) {
                float4 mv[4];
                #pragma unroll
                for (int s = 0; s < 4; s++)
                    mv[s] = ((const float4*)(m_all + (b0 + s) * 32 + lh * 16))[i4];
                #pragma unroll
                for (int s = 0; s < 4; s++) {
                    int i = i4 * 4;
                    float p0 = w[i].x * dtv[s].x;
                    p0 = fmaf(w[i].y, dtv[s].y, p0);
                    p0 = fmaf(w[i].z, dtv[s].z, p0);
                    p0 = fmaf(w[i].w, dtv[s].w, p0);
                    acc[s] = fmaf(mv[s].x, p0, acc[s]);
                    float p1 = w[i + 1].x * dtv[s].x;
                    p1 = fmaf(w[i + 1].y, dtv[s].y, p1);
                    p1 = fmaf(w[i + 1].z, dtv[s].z, p1);
                    p1 = fmaf(w[i + 1].w, dtv[s].w, p1);
                    acc[s] = fmaf(mv[s].y, p1, acc[s]);
                    float p2 = w[i + 2].x * dtv[s].x;
                    p2 = fmaf(w[i + 2].y, dtv[s].y, p2);
                    p2 = fmaf(w[i + 2].z, dtv[s].z, p2);
                    p2 = fmaf(w[i + 2].w, dtv[s].w, p2);
                    acc[s] = fmaf(mv[s].z, p2, acc[s]);
                    float p3 = w[i + 3].x * dtv[s].x;
                    p3 = fmaf(w[i + 3].y, dtv[s].y, p3);
                    p3 = fmaf(w[i + 3].z, dtv[s].z, p3);
                    p3 = fmaf(w[i + 3].w, dtv[s].w, p3);
                    acc[s] = fmaf(mv[s].w, p3, acc[s]);
                }
            }
            #pragma unroll
            for (int s = 0; s < 4; s++) {
                float a = acc[s];
                a += __shfl_xor_sync(0xffffffffu, a, 1);
                a += __shfl_xor_sync(0xffffffffu, a, 2);
                a += __shfl_xor_sync(0xffffffffu, a, 4);
                a += __shfl_xor_sync(0xffffffffu, a, 8);
                if (l == 0) u_sh[cur * 128 + s * 32 + o] = a;
            }
        }

        if (grp >= 1) {
            int gb = (grp - 1) * 4;
            int pv = (grp - 1) & 1;
            if (tid < 128) {
                float bu[4] = {0.f, 0.f, 0.f, 0.f};
                float ed[4] = {0.f, 0.f, 0.f, 0.f};
                #pragma unroll
                for (int oo = 0; oo < 32; oo++) {
                    float wbv = wb_sh[oo * 128 + tid];
                    float wev = we_sh[oo * 128 + tid];
                    #pragma unroll
                    for (int s = 0; s < 4; s++) {
                        bu[s] = fmaf(u_sh[pv * 128 + s * 32 + oo], wbv, bu[s]);
                        ed[s] = fmaf(d_all[(gb + s) * 32 + oo], wev, ed[s]);
                    }
                }
                float dn = dxmn_sh[tid], dx = dxmx_sh[tid];
                float bv = bvec_sh[tid];
                #pragma unroll
                for (int s = 0; s < 4; s++) {
                    size_t base128 = ((size_t)t * Bc + (gb + s)) * 128;
                    out[OFF_SDXU + base128 + tid] = relu_f(dn - bu[s]) + relu_f(bu[s] - dx);
                    out[OFF_SDXD + base128 + tid] = relu_f(dn - ed[s]) + relu_f(ed[s] - dx);
                    g_C[base128 + tid] = bu[s] + ed[s] + bv;
                }
            } else if (uo >= 0 && uo < 32) {
                #pragma unroll
                for (int s = 0; s < 4; s++) {
                    float uu = u_sh[pv * 128 + s * 32 + uo];
                    size_t base32 = tb + (size_t)(gb + s) * 32;
                    out[OFF_U + base32 + uo]     = uu;
                    out[OFF_SUMIN + base32 + uo] = relu_f(umn_c[s] - uu);
                    out[OFF_SUMAX + base32 + uo] = relu_f(uu - umx_c[s]);
                }
            }
        }
        if (uo >= 0 && uo < 32) {
            #pragma unroll
            for (int s = 0; s < 4; s++) { umn_c[s] = umn_n[s]; umx_c[s] = umx_n[s]; }
        }
        __syncthreads();
    }
}

// ---------------- kernel: C2 = Ceven @ WA + Codd  (register-tiled GEMM) ------
#define SM_C2_BYTES ((64*128 + 128*128) * 4)
__global__ void __launch_bounds__(256) k_c2(const float* __restrict__ Cg)
{
    extern __shared__ float smc[];
    float* Xs = smc;            // 64 x 128
    float* Ws = smc + 8192;     // 128 x 128
    int tid = threadIdx.x;
    int p = blockIdx.x >> 1;
    int half = blockIdx.x & 1;

    {
        const float4* wsrc = (const float4*)g_WA;
        float4* wdst = (float4*)Ws;
        #pragma unroll
        for (int i = 0; i < 16; i++) wdst[tid + i * 256] = wsrc[tid + i * 256];
        const float4* xsrc = (const float4*)(Cg + ((size_t)(2 * p) * Bc + half * 64) * 128);
        float4* xdst = (float4*)Xs;
        #pragma unroll
        for (int i = 0; i < 8; i++) xdst[tid + i * 256] = xsrc[tid + i * 256];
    }
    __syncthreads();

    int rg = tid >> 4;
    int cg = tid & 15;
    float acc[4][8];
    #pragma unroll
    for (int i = 0; i < 4; i++)
        #pragma unroll
        for (int c = 0; c < 8; c++) acc[i][c] = 0.0f;

    const float4* Xf4 = (const float4*)Xs;
    const float4* Wf4 = (const float4*)Ws;
    #pragma unroll 8
    for (int k4 = 0; k4 < 32; k4++) {
        float4 wv[4][2];
        #pragma unroll
        for (int kk = 0; kk < 4; kk++) {
            wv[kk][0] = Wf4[(k4 * 4 + kk) * 32 + cg * 2];
            wv[kk][1] = Wf4[(k4 * 4 + kk) * 32 + cg * 2 + 1];
        }
        #pragma unroll
        for (int i = 0; i < 4; i++) {
            float4 xv = Xf4[(rg * 4 + i) * 32 + k4];
            #pragma unroll
            for (int hc = 0; hc < 2; hc++) {
                acc[i][hc * 4 + 0] = fmaf(xv.x, wv[0][hc].x, acc[i][hc * 4 + 0]);
                acc[i][hc * 4 + 1] = fmaf(xv.x, wv[0][hc].y, acc[i][hc * 4 + 1]);
                acc[i][hc * 4 + 2] = fmaf(xv.x, wv[0][hc].z, acc[i][hc * 4 + 2]);
                acc[i][hc * 4 + 3] = fmaf(xv.x, wv[0][hc].w, acc[i][hc * 4 + 3]);
                acc[i][hc * 4 + 0] = fmaf(xv.y, wv[1][hc].x, acc[i][hc * 4 + 0]);
                acc[i][hc * 4 + 1] = fmaf(xv.y, wv[1][hc].y, acc[i][hc * 4 + 1]);
                acc[i][hc * 4 + 2] = fmaf(xv.y, wv[1][hc].z, acc[i][hc * 4 + 2]);
                acc[i][hc * 4 + 3] = fmaf(xv.y, wv[1][hc].w, acc[i][hc * 4 + 3]);
                acc[i][hc * 4 + 0] = fmaf(xv.z, wv[2][hc].x, acc[i][hc * 4 + 0]);
                acc[i][hc * 4 + 1] = fmaf(xv.z, wv[2][hc].y, acc[i][hc * 4 + 1]);
                acc[i][hc * 4 + 2] = fmaf(xv.z, wv[2][hc].z, acc[i][hc * 4 + 2]);
                acc[i][hc * 4 + 3] = fmaf(xv.z, wv[2][hc].w, acc[i][hc * 4 + 3]);
                acc[i][hc * 4 + 0] = fmaf(xv.w, wv[3][hc].x, acc[i][hc * 4 + 0]);
                acc[i][hc * 4 + 1] = fmaf(xv.w, wv[3][hc].y, acc[i][hc * 4 + 1]);
                acc[i][hc * 4 + 2] = fmaf(xv.w, wv[3][hc].z, acc[i][hc * 4 + 2]);
                acc[i][hc * 4 + 3] = fmaf(xv.w, wv[3][hc].w, acc[i][hc * 4 + 3]);
            }
        }
    }

    const float* codd = Cg + ((size_t)(2 * p + 1) * Bc + half * 64) * 128;
    float* o = g_C2 + ((size_t)p * Bc + half * 64) * 128;
    #pragma unroll
    for (int i = 0; i < 4; i++) {
        int row = rg * 4 + i;
        const float4* co = (const float4*)(codd + row * 128) + cg * 2;
        float4* od = (float4*)(o + row * 128) + cg * 2;
        float4 c0 = co[0], c1 = co[1];
        od[0] = make_float4(acc[i][0] + c0.x, acc[i][1] + c0.y,
                            acc[i][2] + c0.z, acc[i][3] + c0.w);
        od[1] = make_float4(acc[i][4] + c1.x, acc[i][5] + c1.y,
                            acc[i][6] + c1.z, acc[i][7] + c1.w);
    }
}

// ---------------- kernel: per-segment local offset D_L -----------------------
// 896 blocks (7 segs x 128 batch). D_{k+2} = D_k @ WA2 + C2, 64 phases, one
// matvec per phase. Writes only the final D_128 to g_DL.
__global__ void __launch_bounds__(256) k_scanlocal(const float* __restrict__ C2g)
{
    __shared__ float dbuf[2][128];
    int tid = threadIdx.x;
    int s = blockIdx.x >> 7, b = blockIdx.x & 127;
    int j = tid >> 1, h = tid & 1;
    int P0 = s * 64;

    float wa2[64];
    #pragma unroll
    for (int kk = 0; kk < 64; kk++) wa2[kk] = g_WA2[(h * 64 + kk) * 128 + j];

    if (h == 0) dbuf[0][j] = 0.0f;
    float cR[2];
    cR[0] = C2g[((size_t)(P0 + 0) * Bc + b) * 128 + j];
    cR[1] = C2g[((size_t)(P0 + 1) * Bc + b) * 128 + j];
    __syncthreads();

    for (int m = 0; m < 64; m++) {
        int cur = m & 1;
        const float4* d4 = ((const float4*)dbuf[cur]) + h * 16;
        float a0 = 0.f, a1 = 0.f;
        #pragma unroll
        for (int kk = 0; kk < 16; kk++) {
            float4 dv = d4[kk];
            a0 = fmaf(dv.x, wa2[kk * 4 + 0], a0);
            a1 = fmaf(dv.y, wa2[kk * 4 + 1], a1);
            a0 = fmaf(dv.z, wa2[kk * 4 + 2], a0);
            a1 = fmaf(dv.w, wa2[kk * 4 + 3], a1);
        }
        float part = a0 + a1;
        float po = __shfl_xor_sync(0xffffffffu, part, 1);
        float dn = part + po + cR[cur];
        if (h == 0) dbuf[1 - cur][j] = dn;
        if (m + 2 < 64)
            cR[cur] = C2g[((size_t)(P0 + m + 2) * Bc + b) * 128 + j];
        __syncthreads();
    }
    if (tid < 128) g_DL[(s * Bc + b) * 128 + tid] = dbuf[0][tid];
}

// ---------------- kernel: boundary scan over segments ------------------------
// 128 blocks (batch). xseg[0] = x0; xseg[s+1] = xseg[s] @ WA128 + DL[s].
__global__ void __launch_bounds__(128) k_scanb()
{
    __shared__ float xs[128];
    int b = blockIdx.x, j = threadIdx.x;
    float w[128];
    #pragma unroll
    for (int k = 0; k < 128; k++) w[k] = g_WA128[k * 128 + j];
    float xv = g_x0[b * 128 + j];
    xs[j] = xv;
    g_xseg[(0 * Bc + b) * 128 + j] = xv;
    __syncthreads();
    for (int s = 0; s < NSEG - 1; s++) {
        float acc = 0.0f;
        #pragma unroll 8
        for (int k = 0; k < 128; k++) acc = fmaf(xs[k], w[k], acc);
        float xn = acc + g_DL[(s * Bc + b) * 128 + j];
        __syncthreads();
        xs[j] = xn;
        g_xseg[((s + 1) * Bc + b) * 128 + j] = xn;
        __syncthreads();
    }
}

// ---------------- kernel: per-segment rollout (R12 core, seeded) -------------
// 1024 blocks (8 segs x 128 batch), 64 phases of 2 steps each.
__global__ void __launch_bounds__(256) k_seqseg(
    const float* __restrict__ XMIN, const float* __restrict__ XMAX,
    const float* __restrict__ Cg, float* __restrict__ out)
{
    __shared__ float xbuf[2][128];
    int tid = threadIdx.x;
    int s = blockIdx.x >> 7, b = blockIdx.x & 127;
    int j = tid >> 1, h = tid & 1;
    int P0 = s * 64;

    float wa[64], wa2[64];
    #pragma unroll
    for (int kk = 0; kk < 64; kk++) {
        wa[kk]  = g_WA [(h * 64 + kk) * 128 + j];
        wa2[kk] = g_WA2[(h * 64 + kk) * 128 + j];
    }

    float xprev = g_xseg[(s * Bc + b) * 128 + j];
    if (h == 0) xbuf[0][j] = xprev;

    float cA[2], mnr[2], mxr[2];
    #pragma unroll
    for (int pp = 0; pp < 2; pp++) {
        int ts = 2 * (P0 + pp) + h;
        size_t ib = ((size_t)ts * Bc + b) * 128 + j;
        mnr[pp] = XMIN[ib];
        mxr[pp] = XMAX[ib];
        cA[pp] = h ? g_C2[((size_t)(P0 + pp) * Bc + b) * 128 + j] : Cg[ib];
    }
    __syncthreads();

    for (int p = 0; p < 64; p++) {
        int cur = p & 1;
        const float4* x4 = ((const float4*)xbuf[cur]) + h * 16;
        float p1a = 0.f, p1b = 0.f, p2a = 0.f, p2b = 0.f;
        #pragma unroll
        for (int kk = 0; kk < 16; kk++) {
            float4 xv = x4[kk];
            p1a = fmaf(xv.x, wa[kk * 4 + 0], p1a);
            p1b = fmaf(xv.y, wa[kk * 4 + 1], p1b);
            p1a = fmaf(xv.z, wa[kk * 4 + 2], p1a);
            p1b = fmaf(xv.w, wa[kk * 4 + 3], p1b);
            p2a = fmaf(xv.x, wa2[kk * 4 + 0], p2a);
            p2b = fmaf(xv.y, wa2[kk * 4 + 1], p2b);
            p2a = fmaf(xv.z, wa2[kk * 4 + 2], p2a);
            p2b = fmaf(xv.w, wa2[kk * 4 + 3], p2b);
        }
        float y1p = p1a + p1b, y2p = p2a + p2b;
        float y1o = __shfl_xor_sync(0xffffffffu, y1p, 1);
        float y2o = __shfl_xor_sync(0xffffffffu, y2p, 1);
        float cmine = cA[cur];
        float coth  = __shfl_xor_sync(0xffffffffu, cmine, 1);
        float ct = h ? coth : cmine;
        float c2 = h ? cmine : coth;
        float y1 = y1p + y1o + ct;
        float y2 = y2p + y2o + c2;

        int ts = 2 * (P0 + p) + h;
        size_t bi = ((size_t)ts * Bc + b) * 128 + j;
        float yv = h ? y2 : y1;
        out[OFF_X + bi]     = yv;
        out[OFF_SXMIN + bi] = relu_f(mnr[cur] - yv);
        out[OFF_SXMAX + bi] = relu_f(yv - mxr[cur]);
        out[OFF_SDXX + bi]  = h ? (y2 - y1) : (y1 - xprev);
        xprev = y2;
        if (h == 0) xbuf[1 - cur][j] = y2;

        if (p + 2 < 64) {
            int tn = 2 * (P0 + p + 2) + h;
            size_t ib = ((size_t)tn * Bc + b) * 128 + j;
            mnr[cur] = XMIN[ib];
            mxr[cur] = XMAX[ib];
            cA[cur] = h ? g_C2[((size_t)(P0 + p + 2) * Bc + b) * 128 + j] : Cg[ib];
        }
        __syncthreads();
    }
}

// ---------------- kernel 6: Y = X @ W_C (register-tiled GEMM) ----------------
#define SM_POST_BYTES ((64*128 + 128*64) * 4)
__global__ void __launch_bounds__(256) k_post(float* __restrict__ out)
{
    extern __shared__ float smp[];
    float* Xs = smp;            // 64 x 128
    float* Ws = smp + 8192;     // 128 x 64
    int tid = threadIdx.x;
    size_t row0 = (size_t)blockIdx.x * 64;

    {
        const float4* wsrc = (const float4*)g_WC;
        float4* wdst = (float4*)Ws;
        #pragma unroll
        for (int i = 0; i < 8; i++) wdst[tid + i * 256] = wsrc[tid + i * 256];
        const float4* xsrc = (const float4*)(out + OFF_X + row0 * 128);
        float4* xdst = (float4*)Xs;
        #pragma unroll
        for (int i = 0; i < 8; i++) xdst[tid + i * 256] = xsrc[tid + i * 256];
    }
    __syncthreads();

    int rg = tid >> 4;
    int cg = tid & 15;
    float acc[4][4];
    #pragma unroll
    for (int i = 0; i < 4; i++)
        #pragma unroll
        for (int c = 0; c < 4; c++) acc[i][c] = 0.0f;

    const float4* Xf4 = (const float4*)Xs;
    const float4* Wf4 = (const float4*)Ws;
    #pragma unroll 8
    for (int k4 = 0; k4 < 32; k4++) {
        float4 wvv[4];
        #pragma unroll
        for (int kk = 0; kk < 4; kk++)
            wvv[kk] = Wf4[(k4 * 4 + kk) * 16 + cg];
        #pragma unroll
        for (int i = 0; i < 4; i++) {
            float4 xv = Xf4[(rg * 4 + i) * 32 + k4];
            acc[i][0] = fmaf(xv.x, wvv[0].x, acc[i][0]);
            acc[i][1] = fmaf(xv.x, wvv[0].y, acc[i][1]);
            acc[i][2] = fmaf(xv.x, wvv[0].z, acc[i][2]);
            acc[i][3] = fmaf(xv.x, wvv[0].w, acc[i][3]);
            acc[i][0] = fmaf(xv.y, wvv[1].x, acc[i][0]);
            acc[i][1] = fmaf(xv.y, wvv[1].y, acc[i][1]);
            acc[i][2] = fmaf(xv.y, wvv[1].z, acc[i][2]);
            acc[i][3] = fmaf(xv.y, wvv[1].w, acc[i][3]);
            acc[i][0] = fmaf(xv.z, wvv[2].x, acc[i][0]);
            acc[i][1] = fmaf(xv.z, wvv[2].y, acc[i][1]);
            acc[i][2] = fmaf(xv.z, wvv[2].z, acc[i][2]);
            acc[i][3] = fmaf(xv.z, wvv[2].w, acc[i][3]);
            acc[i][0] = fmaf(xv.w, wvv[3].x, acc[i][0]);
            acc[i][1] = fmaf(xv.w, wvv[3].y, acc[i][1]);
            acc[i][2] = fmaf(xv.w, wvv[3].z, acc[i][2]);
            acc[i][3] = fmaf(xv.w, wvv[3].w, acc[i][3]);
        }
    }

    #pragma unroll
    for (int i = 0; i < 4; i++) {
        float4* od = (float4*)(out + OFF_Y + (row0 + rg * 4 + i) * 64) + cg;
        od[0] = make_float4(acc[i][0], acc[i][1], acc[i][2], acc[i][3]);
    }
}

// ---------------- launch ------------------------------------------------------
extern "C" void kernel_launch(void* const* d_in, const int* in_sizes, int n_in,
                              void* d_out, int out_size)
{
    const float* Ym   = (const float*)d_in[0];
    const float* M    = (const float*)d_in[1];
    const float* DTin = (const float*)d_in[2];
    const float* Din  = (const float*)d_in[3];
    const float* XMIN = (const float*)d_in[4];
    const float* XMAX = (const float*)d_in[5];
    const float* UMIN = (const float*)d_in[6];
    const float* UMAX = (const float*)d_in[7];
    const float* x0c  = (const float*)d_in[8];
    const float* UA   = (const float*)d_in[9];
    const float* sigA = (const float*)d_in[10];
    const float* VA   = (const float*)d_in[11];
    const float* UC   = (const float*)d_in[12];
    const float* sigC = (const float*)d_in[13];
    const float* VC   = (const float*)d_in[14];
    const float* wE   = (const float*)d_in[15];
    const float* sE   = (const float*)d_in[16];
    const float* wB   = (const float*)d_in[17];
    const float* Whf  = (const float*)d_in[18];
    const float* Wih  = (const float*)d_in[19];
    const float* Whh  = (const float*)d_in[20];
    const float* dxmn = (const float*)d_in[21];
    const float* dxmx = (const float*)d_in[22];
    float* out = (float*)d_out;

    static const size_t smem_pre = SM_PRE_FLOATS * sizeof(float);
    cudaFuncSetAttribute(k_pre, cudaFuncAttributeMaxDynamicSharedMemorySize,
                         (int)smem_pre);
    cudaFuncSetAttribute(k_c2, cudaFuncAttributeMaxDynamicSharedMemorySize,
                         SM_C2_BYTES);
    cudaFuncSetAttribute(k_post, cudaFuncAttributeMaxDynamicSharedMemorySize,
                         SM_POST_BYTES);

    float *Cg, *C2g, *WA2p, *T1p, *T2p, *WA128p;
    cudaGetSymbolAddress((void**)&Cg, g_C);
    cudaGetSymbolAddress((void**)&C2g, g_C2);
    cudaGetSymbolAddress((void**)&WA2p, g_WA2);
    cudaGetSymbolAddress((void**)&T1p, g_T1);
    cudaGetSymbolAddress((void**)&T2p, g_T2);
    cudaGetSymbolAddress((void**)&WA128p, g_WA128);

    k_setup<<<128, 128>>>(UA, sigA, VA, UC, sigC, VC);
    k_setup2<<<1, 128>>>(x0c, wE, sE, wB, out);
    k_wa2<<<128, 128>>>();
    k_pre<<<NSTEPSc, 512, smem_pre>>>(M, DTin, Din, UMIN, UMAX, Whf, dxmn, dxmx, out);
    k_matsq<<<128, 128>>>(WA2p, T1p);     // WA^4
    k_matsq<<<128, 128>>>(T1p, T2p);      // WA^8
    k_matsq<<<128, 128>>>(T2p, T1p);      // WA^16
    k_matsq<<<128, 128>>>(T1p, T2p);      // WA^32
    k_matsq<<<128, 128>>>(T2p, T1p);      // WA^64
    k_matsq<<<128, 128>>>(T1p, WA128p);   // WA^128
    k_rnn<<<Bc, 512>>>(Ym, Wih, Whh);
    k_c2<<<NSTEPSc, 256, SM_C2_BYTES>>>(Cg);
    k_scanlocal<<<(NSEG - 1) * Bc, 256>>>(C2g);
    k_scanb<<<Bc, 128>>>();
    k_seqseg<<<NSEG * Bc, 256>>>(XMIN, XMAX, Cg, out);
    k_post<<<(NSTEPSc * Bc) / 64, 256, SM_POST_BYTES>>>(out);
}

// round 15
// speedup vs baseline: 1.2959x; 1.1287x over previous
#include <cuda_runtime.h>
#include <math.h>

// Problem dims
#define NXc 128
#define NYc 64
#define NMc 32
#define NDTc 32
#define NUc 32
#define NDc 32
#define NSTEPSc 1024
#define Bc 128
#define TPc 64
#define NSEG 8

// Output offsets (floats) for the flattened 11-tuple
#define OFF_X      ((size_t)0)
#define OFF_Y      ((size_t)16777216)
#define OFF_U      ((size_t)25165824)
#define OFF_SXMIN  ((size_t)29360128)
#define OFF_SXMAX  ((size_t)46137344)
#define OFF_SUMIN  ((size_t)62914560)
#define OFF_SUMAX  ((size_t)67108864)
#define OFF_SDXX   ((size_t)71303168)
#define OFF_SDXU   ((size_t)88080384)
#define OFF_SDXD   ((size_t)104857600)
#define OFF_SPECT  ((size_t)121634816)

// ---------------- module-scope scratch ----------------
__device__ float g_WA[NXc * NXc];
__device__ float g_WA2[NXc * NXc];
__device__ float g_T1[NXc * NXc];
__device__ float g_T2[NXc * NXc];
__device__ float g_WA128[NXc * NXc];
__device__ float g_WC[NXc * NYc];
__device__ float g_WE[NDc * NXc];
__device__ float g_WB[NUc * NXc];
__device__ float g_bvec[NXc];
__device__ float g_x0[Bc * NXc];
__device__ float g_C[(size_t)NSTEPSc * Bc * NXc];        // 64 MB
__device__ float g_C2[(size_t)(NSTEPSc / 2) * Bc * NXc]; // 32 MB
__device__ float g_DL[(NSEG - 1) * Bc * NXc];
__device__ float g_xseg[NSEG * Bc * NXc];
__device__ float g_accP[128 * 8];

__device__ __forceinline__ float sigmoid_f(float x) { return 1.0f / (1.0f + expf(-x)); }
__device__ __forceinline__ float relu_f(float x) { return fmaxf(x, 0.0f); }
__device__ __forceinline__ float gelu_tanh(float x) {
    float x3 = x * x * x;
    float t = tanhf(0.7978845608028654f * (x + 0.044715f * x3));
    return 0.5f * x * (1.0f + t);
}

// ---------------- kernel 1: spectral weights + Gram partials -----------------
__global__ void __launch_bounds__(128) k_setup(
    const float* __restrict__ UA, const float* __restrict__ sigA, const float* __restrict__ VA,
    const float* __restrict__ UC, const float* __restrict__ sigC, const float* __restrict__ VC)
{
    __shared__ float sA[128], sC[64], rowUA[128], rowUC[64];
    __shared__ float colUA[128], colVA[128], colUC[128], colVC[64];
    __shared__ float red[4];
    int i = blockIdx.x, j = threadIdx.x;

    sA[j] = 0.1f + 0.8f * sigmoid_f(sigA[j]);
    rowUA[j] = UA[i * 128 + j];
    colUA[j] = UA[j * 128 + i];
    colVA[j] = VA[j * 128 + i];
    colUC[j] = UC[j * 128 + i];
    if (j < 64) {
        sC[j] = 0.9f + 0.1f * sigmoid_f(sigC[j]);
        rowUC[j] = UC[i * 128 + j];
        if (i < 64) colVC[j] = VC[j * 64 + i];
    }
    __syncthreads();

    float acc = 0.0f;
    #pragma unroll 8
    for (int k = 0; k < 128; k++) acc = fmaf(rowUA[k] * sA[k], VA[k * 128 + j], acc);
    g_WA[i * 128 + j] = acc;

    if (j < 64) {
        float a = 0.0f;
        #pragma unroll 8
        for (int k = 0; k < 64; k++) a = fmaf(rowUC[k] * sC[k], VC[k * 64 + j], a);
        g_WC[i * 64 + j] = a;
    }

    float gua = 0.0f, gva = 0.0f, guc = 0.0f;
    #pragma unroll 8
    for (int k = 0; k < 128; k++) {
        gua = fmaf(colUA[k], UA[k * 128 + j], gua);
        gva = fmaf(colVA[k], VA[k * 128 + j], gva);
        guc = fmaf(colUC[k], UC[k * 128 + j], guc);
    }
    float p6 = 0.0f, p7 = 0.0f;
    if (i < 64 && j < 64) {
        float g = 0.0f;
        #pragma unroll 8
        for (int k = 0; k < 64; k++) g = fmaf(colVC[k], VC[k * 64 + j], g);
        p6 = g * g;
        float v = VC[i * 64 + j];
        p7 = v * v;
    }
    float part[8];
    part[0] = gua * gua;
    part[1] = rowUA[j] * rowUA[j];
    part[2] = gva * gva;
    { float v = VA[i * 128 + j]; part[3] = v * v; }
    part[4] = guc * guc;
    { float v = UC[i * 128 + j]; part[5] = v * v; }
    part[6] = p6;
    part[7] = p7;

    for (int v = 0; v < 8; v++) {
        float x = part[v];
        #pragma unroll
        for (int o = 16; o; o >>= 1) x += __shfl_xor_sync(0xffffffffu, x, o);
        if ((j & 31) == 0) red[j >> 5] = x;
        __syncthreads();
        if (j == 0) g_accP[i * 8 + v] = red[0] + red[1] + red[2] + red[3];
        __syncthreads();
    }
}

// ---------------- kernel 2: W_E, W_B, bvec, SpectErr -------------------------
__global__ void __launch_bounds__(128) k_setup2(
    const float* __restrict__ x0c, const float* __restrict__ wE,
    const float* __restrict__ sE, const float* __restrict__ wB,
    float* __restrict__ out)
{
    __shared__ float xc[128];
    __shared__ float acc8[8];
    int j = threadIdx.x;
    xc[j] = x0c[j];
    if (j < 8) {
        float s = 0.0f;
        for (int i = 0; i < 128; i++) s += g_accP[i * 8 + j];
        acc8[j] = s;
    }
    __syncthreads();

    float b = 0.0f;
    #pragma unroll 8
    for (int k = 0; k < 128; k++) b = fmaf(xc[k], g_WA[k * 128 + j], b);
    g_bvec[j] = b;

    float mx = -1e30f;
    for (int i = 0; i < 32; i++) mx = fmaxf(mx, wE[i * 128 + j]);
    float s = 0.0f;
    for (int i = 0; i < 32; i++) s += expf(wE[i * 128 + j] - mx);
    float inv = 1.0f / s;
    for (int i = 0; i < 32; i++) {
        float sm = expf(wE[i * 128 + j] - mx) * inv;
        float sc = 1.0f - 0.95f * sigmoid_f(sE[i * 128 + j]);
        g_WE[i * 128 + j] = sc * sm;
    }
    for (int idx = j; idx < NUc * NXc; idx += 128) g_WB[idx] = relu_f(wB[idx]);

    float errA = (acc8[0] - 2.0f * acc8[1] + 128.0f) * (1.0f / 16384.0f)
               + (acc8[2] - 2.0f * acc8[3] + 128.0f) * (1.0f / 16384.0f);
    float errC = (acc8[4] - 2.0f * acc8[5] + 128.0f) * (1.0f / 16384.0f)
               + (acc8[6] - 2.0f * acc8[7] + 64.0f) * (1.0f / 4096.0f);
    float sp = errA + errC;
    for (int idx = j; idx < NSTEPSc; idx += 128) out[OFF_SPECT + idx] = sp;
}

// ---------------- kernel: WA2 = WA @ WA --------------------------------------
__global__ void __launch_bounds__(128) k_wa2() {
    __shared__ float rowA[128];
    int i = blockIdx.x, j = threadIdx.x;
    rowA[j] = g_WA[i * 128 + j];
    __syncthreads();
    float acc = 0.0f;
    #pragma unroll 8
    for (int k = 0; k < 128; k++) acc = fmaf(rowA[k], g_WA[k * 128 + j], acc);
    g_WA2[i * 128 + j] = acc;
}

// ---------------- kernel: O = A @ A ------------------------------------------
__global__ void __launch_bounds__(128) k_matsq(
    const float* __restrict__ A, float* __restrict__ O)
{
    __shared__ float rowA[128];
    int i = blockIdx.x, j = threadIdx.x;
    rowA[j] = A[i * 128 + j];
    __syncthreads();
    float acc = 0.0f;
    #pragma unroll 8
    for (int k = 0; k < 128; k++) acc = fmaf(rowA[k], A[k * 128 + j], acc);
    O[i * 128 + j] = acc;
}

// ---------------- kernel 3: RNN warmup (proven version) ----------------------
__global__ void __launch_bounds__(512) k_rnn(
    const float* __restrict__ Ym, const float* __restrict__ Wih,
    const float* __restrict__ Whh)
{
    __shared__ float h_sh[128];
    __shared__ float ym_sh[2][64];
    __shared__ float p_sh[3 * 128];
    int tid = threadIdx.x;
    int b = blockIdx.x;
    int j = tid & 127, h = tid >> 7;

    float whh_r[32];
    #pragma unroll
    for (int kk = 0; kk < 32; kk++) whh_r[kk] = Whh[(h * 32 + kk) * 128 + j];
    float wih_r[16];
    #pragma unroll
    for (int kk = 0; kk < 16; kk++) wih_r[kk] = Wih[(h * 16 + kk) * 128 + j];

    if (tid < 128) h_sh[tid] = 0.0f;
    if (tid >= 448) ym_sh[0][tid - 448] = Ym[(size_t)b * 64 + (tid - 448)];
    __syncthreads();

    for (int t = 0; t < TPc; t++) {
        const float* yc = ym_sh[t & 1];
        float acc = 0.0f;
        #pragma unroll
        for (int kk = 0; kk < 16; kk++)
            acc = fmaf(yc[h * 16 + kk], wih_r[kk], acc);
        #pragma unroll
        for (int kk = 0; kk < 32; kk++)
            acc = fmaf(h_sh[h * 32 + kk], whh_r[kk], acc);

        if (tid >= 448 && t + 1 < TPc)
            ym_sh[(t + 1) & 1][tid - 448] = Ym[((size_t)(t + 1) * Bc + b) * 64 + (tid - 448)];

        if (h) p_sh[(h - 1) * 128 + j] = acc;
        __syncthreads();
        if (h == 0)
            h_sh[j] = gelu_tanh(acc + p_sh[j] + p_sh[128 + j] + p_sh[256 + j]);
        __syncthreads();
    }
    if (tid < 128) g_x0[b * 128 + tid] = h_sh[tid];
}

// ---------------- kernel 4: precompute, 4-sample batched (R8/R9 proven) ------
#define SM_PRE_FLOATS (4096*3 + 4096*2 + 256 + 128*3)
__global__ void __launch_bounds__(512) k_pre(
    const float* __restrict__ M, const float* __restrict__ DTin,
    const float* __restrict__ Din, const float* __restrict__ UMIN,
    const float* __restrict__ UMAX, const float* __restrict__ Whf,
    const float* __restrict__ dxmn_g, const float* __restrict__ dxmx_g,
    float* __restrict__ out)
{
    extern __shared__ float sm[];
    float* m_all   = sm;             // 4096
    float* dt_all  = sm + 4096;      // 4096
    float* d_all   = sm + 8192;      // 4096
    float* wb_sh   = sm + 12288;     // 4096
    float* we_sh   = sm + 16384;     // 4096
    float* u_sh    = sm + 20480;     // 2 x 128
    float* bvec_sh = sm + 20736;     // 128
    float* dxmn_sh = sm + 20864;     // 128
    float* dxmx_sh = sm + 20992;     // 128

    int tid = threadIdx.x;
    int t = blockIdx.x;
    int o = tid >> 4, l = tid & 15;
    int lh = l >> 3, lj = l & 7;

    float4 w[16];
    const float4* whf4 = (const float4*)Whf;
    #pragma unroll
    for (int i = 0; i < 16; i++)
        w[i] = whf4[(o * 32 + lh * 16 + i) * 8 + lj];

    size_t tb = (size_t)t * 4096;
    {
        const float4* M4  = (const float4*)(M + tb);
        const float4* DT4 = (const float4*)(DTin + tb);
        const float4* D4  = (const float4*)(Din + tb);
        float4* m4  = (float4*)m_all;
        float4* dt4 = (float4*)dt_all;
        float4* d4  = (float4*)d_all;
        #pragma unroll
        for (int idx = tid; idx < 1024; idx += 512) {
            m4[idx] = M4[idx];
            dt4[idx] = DT4[idx];
            d4[idx] = D4[idx];
        }
    }
    for (int idx = tid; idx < 4096; idx += 512) {
        wb_sh[idx] = g_WB[idx];
        we_sh[idx] = g_WE[idx];
    }
    if (tid < 128) {
        bvec_sh[tid] = g_bvec[tid];
        dxmn_sh[tid] = dxmn_g[tid];
        dxmx_sh[tid] = dxmx_g[tid];
    }
    int uo = tid - 384;
    float umn_c[4], umx_c[4], umn_n[4], umx_n[4];
    __syncthreads();

    for (int grp = 0; grp <= 32; grp++) {
        int cur = grp & 1;

        if (uo >= 0 && uo < 32 && grp < 32) {
            #pragma unroll
            for (int s = 0; s < 4; s++) {
                size_t idx = tb + (size_t)(grp * 4 + s) * 32 + uo;
                umn_n[s] = UMIN[idx];
                umx_n[s] = UMAX[idx];
            }
        }

        if (grp < 32) {
            int b0 = grp * 4;
            float4 dtv[4];
            #pragma unroll
            for (int s = 0; s < 4; s++)
                dtv[s] = ((const float4*)(dt_all + (b0 + s) * 32))[lj];
            float acc[4] = {0.f, 0.f, 0.f, 0.f};
            #pragma unroll
            for (int i4 = 0; i4 < 4; i4++) {
                float4 mv[4];
                #pragma unroll
                for (int s = 0; s < 4; s++)
                    mv[s] = ((const float4*)(m_all + (b0 + s) * 32 + lh * 16))[i4];
                #pragma unroll
                for (int s = 0; s < 4; s++) {
                    int i = i4 * 4;
                    float p0 = w[i].x * dtv[s].x;
                    p0 = fmaf(w[i].y, dtv[s].y, p0);
                    p0 = fmaf(w[i].z, dtv[s].z, p0);
                    p0 = fmaf(w[i].w, dtv[s].w, p0);
                    acc[s] = fmaf(mv[s].x, p0, acc[s]);
                    float p1 = w[i + 1].x * dtv[s].x;
                    p1 = fmaf(w[i + 1].y, dtv[s].y, p1);
                    p1 = fmaf(w[i + 1].z, dtv[s].z, p1);
                    p1 = fmaf(w[i + 1].w, dtv[s].w, p1);
                    acc[s] = fmaf(mv[s].y, p1, acc[s]);
                    float p2 = w[i + 2].x * dtv[s].x;
                    p2 = fmaf(w[i + 2].y, dtv[s].y, p2);
                    p2 = fmaf(w[i + 2].z, dtv[s].z, p2);
                    p2 = fmaf(w[i + 2].w, dtv[s].w, p2);
                    acc[s] = fmaf(mv[s].z, p2, acc[s]);
                    float p3 = w[i + 3].x * dtv[s].x;
                    p3 = fmaf(w[i + 3].y, dtv[s].y, p3);
                    p3 = fmaf(w[i + 3].z, dtv[s].z, p3);
                    p3 = fmaf(w[i + 3].w, dtv[s].w, p3);
                    acc[s] = fmaf(mv[s].w, p3, acc[s]);
                }
            }
            #pragma unroll
            for (int s = 0; s < 4; s++) {
                float a = acc[s];
                a += __shfl_xor_sync(0xffffffffu, a, 1);
                a += __shfl_xor_sync(0xffffffffu, a, 2);
                a += __shfl_xor_sync(0xffffffffu, a, 4);
                a += __shfl_xor_sync(0xffffffffu, a, 8);
                if (l == 0) u_sh[cur * 128 + s * 32 + o] = a;
            }
        }

        if (grp >= 1) {
            int gb = (grp - 1) * 4;
            int pv = (grp - 1) & 1;
            if (tid < 128) {
                float bu[4] = {0.f, 0.f, 0.f, 0.f};
                float ed[4] = {0.f, 0.f, 0.f, 0.f};
                #pragma unroll
                for (int oo = 0; oo < 32; oo++) {
                    float wbv = wb_sh[oo * 128 + tid];
                    float wev = we_sh[oo * 128 + tid];
                    #pragma unroll
                    for (int s = 0; s < 4; s++) {
                        bu[s] = fmaf(u_sh[pv * 128 + s * 32 + oo], wbv, bu[s]);
                        ed[s] = fmaf(d_all[(gb + s) * 32 + oo], wev, ed[s]);
                    }
                }
                float dn = dxmn_sh[tid], dx = dxmx_sh[tid];
                float bv = bvec_sh[tid];
                #pragma unroll
                for (int s = 0; s < 4; s++) {
                    size_t base128 = ((size_t)t * Bc + (gb + s)) * 128;
                    out[OFF_SDXU + base128 + tid] = relu_f(dn - bu[s]) + relu_f(bu[s] - dx);
                    out[OFF_SDXD + base128 + tid] = relu_f(dn - ed[s]) + relu_f(ed[s] - dx);
                    g_C[base128 + tid] = bu[s] + ed[s] + bv;
                }
            } else if (uo >= 0 && uo < 32) {
                #pragma unroll
                for (int s = 0; s < 4; s++) {
                    float uu = u_sh[pv * 128 + s * 32 + uo];
                    size_t base32 = tb + (size_t)(gb + s) * 32;
                    out[OFF_U + base32 + uo]     = uu;
                    out[OFF_SUMIN + base32 + uo] = relu_f(umn_c[s] - uu);
                    out[OFF_SUMAX + base32 + uo] = relu_f(uu - umx_c[s]);
                }
            }
        }
        if (uo >= 0 && uo < 32) {
            #pragma unroll
            for (int s = 0; s < 4; s++) { umn_c[s] = umn_n[s]; umx_c[s] = umx_n[s]; }
        }
        __syncthreads();
    }
}

// ---------------- kernel: C2 = Ceven @ WA + Codd  (register-tiled GEMM) ------
#define SM_C2_BYTES ((64*128 + 128*128) * 4)
__global__ void __launch_bounds__(256) k_c2(const float* __restrict__ Cg)
{
    extern __shared__ float smc[];
    float* Xs = smc;            // 64 x 128
    float* Ws = smc + 8192;     // 128 x 128
    int tid = threadIdx.x;
    int p = blockIdx.x >> 1;
    int half = blockIdx.x & 1;

    {
        const float4* wsrc = (const float4*)g_WA;
        float4* wdst = (float4*)Ws;
        #pragma unroll
        for (int i = 0; i < 16; i++) wdst[tid + i * 256] = wsrc[tid + i * 256];
        const float4* xsrc = (const float4*)(Cg + ((size_t)(2 * p) * Bc + half * 64) * 128);
        float4* xdst = (float4*)Xs;
        #pragma unroll
        for (int i = 0; i < 8; i++) xdst[tid + i * 256] = xsrc[tid + i * 256];
    }
    __syncthreads();

    int rg = tid >> 4;
    int cg = tid & 15;
    float acc[4][8];
    #pragma unroll
    for (int i = 0; i < 4; i++)
        #pragma unroll
        for (int c = 0; c < 8; c++) acc[i][c] = 0.0f;

    const float4* Xf4 = (const float4*)Xs;
    const float4* Wf4 = (const float4*)Ws;
    #pragma unroll 8
    for (int k4 = 0; k4 < 32; k4++) {
        float4 wv[4][2];
        #pragma unroll
        for (int kk = 0; kk < 4; kk++) {
            wv[kk][0] = Wf4[(k4 * 4 + kk) * 32 + cg * 2];
            wv[kk][1] = Wf4[(k4 * 4 + kk) * 32 + cg * 2 + 1];
        }
        #pragma unroll
        for (int i = 0; i < 4; i++) {
            float4 xv = Xf4[(rg * 4 + i) * 32 + k4];
            #pragma unroll
            for (int hc = 0; hc < 2; hc++) {
                acc[i][hc * 4 + 0] = fmaf(xv.x, wv[0][hc].x, acc[i][hc * 4 + 0]);
                acc[i][hc * 4 + 1] = fmaf(xv.x, wv[0][hc].y, acc[i][hc * 4 + 1]);
                acc[i][hc * 4 + 2] = fmaf(xv.x, wv[0][hc].z, acc[i][hc * 4 + 2]);
                acc[i][hc * 4 + 3] = fmaf(xv.x, wv[0][hc].w, acc[i][hc * 4 + 3]);
                acc[i][hc * 4 + 0] = fmaf(xv.y, wv[1][hc].x, acc[i][hc * 4 + 0]);
                acc[i][hc * 4 + 1] = fmaf(xv.y, wv[1][hc].y, acc[i][hc * 4 + 1]);
                acc[i][hc * 4 + 2] = fmaf(xv.y, wv[1][hc].z, acc[i][hc * 4 + 2]);
                acc[i][hc * 4 + 3] = fmaf(xv.y, wv[1][hc].w, acc[i][hc * 4 + 3]);
                acc[i][hc * 4 + 0] = fmaf(xv.z, wv[2][hc].x, acc[i][hc * 4 + 0]);
                acc[i][hc * 4 + 1] = fmaf(xv.z, wv[2][hc].y, acc[i][hc * 4 + 1]);
                acc[i][hc * 4 + 2] = fmaf(xv.z, wv[2][hc].z, acc[i][hc * 4 + 2]);
                acc[i][hc * 4 + 3] = fmaf(xv.z, wv[2][hc].w, acc[i][hc * 4 + 3]);
                acc[i][hc * 4 + 0] = fmaf(xv.w, wv[3][hc].x, acc[i][hc * 4 + 0]);
                acc[i][hc * 4 + 1] = fmaf(xv.w, wv[3][hc].y, acc[i][hc * 4 + 1]);
                acc[i][hc * 4 + 2] = fmaf(xv.w, wv[3][hc].z, acc[i][hc * 4 + 2]);
                acc[i][hc * 4 + 3] = fmaf(xv.w, wv[3][hc].w, acc[i][hc * 4 + 3]);
            }
        }
    }

    const float* codd = Cg + ((size_t)(2 * p + 1) * Bc + half * 64) * 128;
    float* o = g_C2 + ((size_t)p * Bc + half * 64) * 128;
    #pragma unroll
    for (int i = 0; i < 4; i++) {
        int row = rg * 4 + i;
        const float4* co = (const float4*)(codd + row * 128) + cg * 2;
        float4* od = (float4*)(o + row * 128) + cg * 2;
        float4 c0 = co[0], c1 = co[1];
        od[0] = make_float4(acc[i][0] + c0.x, acc[i][1] + c0.y,
                            acc[i][2] + c0.z, acc[i][3] + c0.w);
        od[1] = make_float4(acc[i][4] + c1.x, acc[i][5] + c1.y,
                            acc[i][6] + c1.z, acc[i][7] + c1.w);
    }
}

// ---------------- kernel: per-segment local offset D_L (batch-4) -------------
// 224 blocks (7 segs x 32 batch-groups). Each block: 4 batches share the
// register-resident WA2 -> 4x FMA per barrier phase.
__global__ void __launch_bounds__(256) k_scanlocal(const float* __restrict__ C2g)
{
    __shared__ float dbuf[2][4][128];
    int tid = threadIdx.x;
    int s = blockIdx.x >> 5, bg = blockIdx.x & 31;
    int b0 = bg * 4;
    int j = tid >> 1, h = tid & 1;
    int P0 = s * 64;

    float wa2[64];
    #pragma unroll
    for (int kk = 0; kk < 64; kk++) wa2[kk] = g_WA2[(h * 64 + kk) * 128 + j];

    if (h == 0) {
        #pragma unroll
        for (int sb = 0; sb < 4; sb++) dbuf[0][sb][j] = 0.0f;
    }
    float cR[2][4];
    #pragma unroll
    for (int pp = 0; pp < 2; pp++)
        #pragma unroll
        for (int sb = 0; sb < 4; sb++)
            cR[pp][sb] = C2g[((size_t)(P0 + pp) * Bc + (b0 + sb)) * 128 + j];
    __syncthreads();

    for (int m = 0; m < 64; m++) {
        int cur = m & 1;
        float a0[4] = {0.f, 0.f, 0.f, 0.f}, a1[4] = {0.f, 0.f, 0.f, 0.f};
        #pragma unroll
        for (int kk = 0; kk < 16; kk++) {
            #pragma unroll
            for (int sb = 0; sb < 4; sb++) {
                float4 dv = ((const float4*)dbuf[cur][sb])[h * 16 + kk];
                a0[sb] = fmaf(dv.x, wa2[kk * 4 + 0], a0[sb]);
                a1[sb] = fmaf(dv.y, wa2[kk * 4 + 1], a1[sb]);
                a0[sb] = fmaf(dv.z, wa2[kk * 4 + 2], a0[sb]);
                a1[sb] = fmaf(dv.w, wa2[kk * 4 + 3], a1[sb]);
            }
        }
        #pragma unroll
        for (int sb = 0; sb < 4; sb++) {
            float part = a0[sb] + a1[sb];
            float po = __shfl_xor_sync(0xffffffffu, part, 1);
            float dn = part + po + cR[cur][sb];
            if (h == 0) dbuf[1 - cur][sb][j] = dn;
        }
        if (m + 2 < 64) {
            #pragma unroll
            for (int sb = 0; sb < 4; sb++)
                cR[cur][sb] = C2g[((size_t)(P0 + m + 2) * Bc + (b0 + sb)) * 128 + j];
        }
        __syncthreads();
    }
    if (tid < 128) {
        #pragma unroll
        for (int sb = 0; sb < 4; sb++)
            g_DL[(s * Bc + (b0 + sb)) * 128 + tid] = dbuf[0][sb][tid];
    }
}

// ---------------- kernel: boundary scan over segments ------------------------
__global__ void __launch_bounds__(128) k_scanb()
{
    __shared__ float xs[128];
    int b = blockIdx.x, j = threadIdx.x;
    float w[128];
    #pragma unroll
    for (int k = 0; k < 128; k++) w[k] = g_WA128[k * 128 + j];
    float xv = g_x0[b * 128 + j];
    xs[j] = xv;
    g_xseg[(0 * Bc + b) * 128 + j] = xv;
    __syncthreads();
    for (int s = 0; s < NSEG - 1; s++) {
        float acc = 0.0f;
        #pragma unroll 8
        for (int k = 0; k < 128; k++) acc = fmaf(xs[k], w[k], acc);
        float xn = acc + g_DL[(s * Bc + b) * 128 + j];
        __syncthreads();
        xs[j] = xn;
        g_xseg[((s + 1) * Bc + b) * 128 + j] = xn;
        __syncthreads();
    }
}

// ---------------- kernel: per-segment rollout (batch-4) ----------------------
// 256 blocks (8 segs x 32 batch-groups), 64 phases of 2 steps x 4 batches.
__global__ void __launch_bounds__(256) k_seqseg(
    const float* __restrict__ XMIN, const float* __restrict__ XMAX,
    const float* __restrict__ Cg, float* __restrict__ out)
{
    __shared__ float xbuf[2][4][128];
    int tid = threadIdx.x;
    int s = blockIdx.x >> 5, bg = blockIdx.x & 31;
    int b0 = bg * 4;
    int j = tid >> 1, h = tid & 1;
    int P0 = s * 64;

    float wa[64], wa2[64];
    #pragma unroll
    for (int kk = 0; kk < 64; kk++) {
        wa[kk]  = g_WA [(h * 64 + kk) * 128 + j];
        wa2[kk] = g_WA2[(h * 64 + kk) * 128 + j];
    }

    float xprev[4];
    #pragma unroll
    for (int sb = 0; sb < 4; sb++) {
        xprev[sb] = g_xseg[(s * Bc + (b0 + sb)) * 128 + j];
        if (h == 0) xbuf[0][sb][j] = xprev[sb];
    }

    float cA[2][4], mnr[2][4], mxr[2][4];
    #pragma unroll
    for (int pp = 0; pp < 2; pp++) {
        #pragma unroll
        for (int sb = 0; sb < 4; sb++) {
            int ts = 2 * (P0 + pp) + h;
            size_t ib = ((size_t)ts * Bc + (b0 + sb)) * 128 + j;
            mnr[pp][sb] = XMIN[ib];
            mxr[pp][sb] = XMAX[ib];
            cA[pp][sb] = h ? g_C2[((size_t)(P0 + pp) * Bc + (b0 + sb)) * 128 + j] : Cg[ib];
        }
    }
    __syncthreads();

    for (int p = 0; p < 64; p++) {
        int cur = p & 1;
        float p1a[4], p1b[4], p2a[4], p2b[4];
        #pragma unroll
        for (int sb = 0; sb < 4; sb++) { p1a[sb] = p1b[sb] = p2a[sb] = p2b[sb] = 0.f; }
        #pragma unroll
        for (int kk = 0; kk < 16; kk++) {
            #pragma unroll
            for (int sb = 0; sb < 4; sb++) {
                float4 xv = ((const float4*)xbuf[cur][sb])[h * 16 + kk];
                p1a[sb] = fmaf(xv.x, wa[kk * 4 + 0], p1a[sb]);
                p1b[sb] = fmaf(xv.y, wa[kk * 4 + 1], p1b[sb]);
                p1a[sb] = fmaf(xv.z, wa[kk * 4 + 2], p1a[sb]);
                p1b[sb] = fmaf(xv.w, wa[kk * 4 + 3], p1b[sb]);
                p2a[sb] = fmaf(xv.x, wa2[kk * 4 + 0], p2a[sb]);
                p2b[sb] = fmaf(xv.y, wa2[kk * 4 + 1], p2b[sb]);
                p2a[sb] = fmaf(xv.z, wa2[kk * 4 + 2], p2a[sb]);
                p2b[sb] = fmaf(xv.w, wa2[kk * 4 + 3], p2b[sb]);
            }
        }
        #pragma unroll
        for (int sb = 0; sb < 4; sb++) {
            float y1p = p1a[sb] + p1b[sb], y2p = p2a[sb] + p2b[sb];
            float y1o = __shfl_xor_sync(0xffffffffu, y1p, 1);
            float y2o = __shfl_xor_sync(0xffffffffu, y2p, 1);
            float cmine = cA[cur][sb];
            float coth  = __shfl_xor_sync(0xffffffffu, cmine, 1);
            float ct = h ? coth : cmine;
            float c2 = h ? cmine : coth;
            float y1 = y1p + y1o + ct;
            float y2 = y2p + y2o + c2;

            int ts = 2 * (P0 + p) + h;
            size_t bi = ((size_t)ts * Bc + (b0 + sb)) * 128 + j;
            float yv = h ? y2 : y1;
            out[OFF_X + bi]     = yv;
            out[OFF_SXMIN + bi] = relu_f(mnr[cur][sb] - yv);
            out[OFF_SXMAX + bi] = relu_f(yv - mxr[cur][sb]);
            out[OFF_SDXX + bi]  = h ? (y2 - y1) : (y1 - xprev[sb]);
            xprev[sb] = y2;
            if (h == 0) xbuf[1 - cur][sb][j] = y2;
        }

        if (p + 2 < 64) {
            #pragma unroll
            for (int sb = 0; sb < 4; sb++) {
                int tn = 2 * (P0 + p + 2) + h;
                size_t ib = ((size_t)tn * Bc + (b0 + sb)) * 128 + j;
                mnr[cur][sb] = XMIN[ib];
                mxr[cur][sb] = XMAX[ib];
                cA[cur][sb] = h ? g_C2[((size_t)(P0 + p + 2) * Bc + (b0 + sb)) * 128 + j]
                                : Cg[ib];
            }
        }
        __syncthreads();
    }
}

// ---------------- kernel 6: Y = X @ W_C (register-tiled GEMM) ----------------
#define SM_POST_BYTES ((64*128 + 128*64) * 4)
__global__ void __launch_bounds__(256) k_post(float* __restrict__ out)
{
    extern __shared__ float smp[];
    float* Xs = smp;            // 64 x 128
    float* Ws = smp + 8192;     // 128 x 64
    int tid = threadIdx.x;
    size_t row0 = (size_t)blockIdx.x * 64;

    {
        const float4* wsrc = (const float4*)g_WC;
        float4* wdst = (float4*)Ws;
        #pragma unroll
        for (int i = 0; i < 8; i++) wdst[tid + i * 256] = wsrc[tid + i * 256];
        const float4* xsrc = (const float4*)(out + OFF_X + row0 * 128);
        float4* xdst = (float4*)Xs;
        #pragma unroll
        for (int i = 0; i < 8; i++) xdst[tid + i * 256] = xsrc[tid + i * 256];
    }
    __syncthreads();

    int rg = tid >> 4;
    int cg = tid & 15;
    float acc[4][4];
    #pragma unroll
    for (int i = 0; i < 4; i++)
        #pragma unroll
        for (int c = 0; c < 4; c++) acc[i][c] = 0.0f;

    const float4* Xf4 = (const float4*)Xs;
    const float4* Wf4 = (const float4*)Ws;
    #pragma unroll 8
    for (int k4 = 0; k4 < 32; k4++) {
        float4 wvv[4];
        #pragma unroll
        for (int kk = 0; kk < 4; kk++)
            wvv[kk] = Wf4[(k4 * 4 + kk) * 16 + cg];
        #pragma unroll
        for (int i = 0; i < 4; i++) {
            float4 xv = Xf4[(rg * 4 + i) * 32 + k4];
            acc[i][0] = fmaf(xv.x, wvv[0].x, acc[i][0]);
            acc[i][1] = fmaf(xv.x, wvv[0].y, acc[i][1]);
            acc[i][2] = fmaf(xv.x, wvv[0].z, acc[i][2]);
            acc[i][3] = fmaf(xv.x, wvv[0].w, acc[i][3]);
            acc[i][0] = fmaf(xv.y, wvv[1].x, acc[i][0]);
            acc[i][1] = fmaf(xv.y, wvv[1].y, acc[i][1]);
            acc[i][2] = fmaf(xv.y, wvv[1].z, acc[i][2]);
            acc[i][3] = fmaf(xv.y, wvv[1].w, acc[i][3]);
            acc[i][0] = fmaf(xv.z, wvv[2].x, acc[i][0]);
            acc[i][1] = fmaf(xv.z, wvv[2].y, acc[i][1]);
            acc[i][2] = fmaf(xv.z, wvv[2].z, acc[i][2]);
            acc[i][3] = fmaf(xv.z, wvv[2].w, acc[i][3]);
            acc[i][0] = fmaf(xv.w, wvv[3].x, acc[i][0]);
            acc[i][1] = fmaf(xv.w, wvv[3].y, acc[i][1]);
            acc[i][2] = fmaf(xv.w, wvv[3].z, acc[i][2]);
            acc[i][3] = fmaf(xv.w, wvv[3].w, acc[i][3]);
        }
    }

    #pragma unroll
    for (int i = 0; i < 4; i++) {
        float4* od = (float4*)(out + OFF_Y + (row0 + rg * 4 + i) * 64) + cg;
        od[0] = make_float4(acc[i][0], acc[i][1], acc[i][2], acc[i][3]);
    }
}

// ---------------- launch ------------------------------------------------------
extern "C" void kernel_launch(void* const* d_in, const int* in_sizes, int n_in,
                              void* d_out, int out_size)
{
    const float* Ym   = (const float*)d_in[0];
    const float* M    = (const float*)d_in[1];
    const float* DTin = (const float*)d_in[2];
    const float* Din  = (const float*)d_in[3];
    const float* XMIN = (const float*)d_in[4];
    const float* XMAX = (const float*)d_in[5];
    const float* UMIN = (const float*)d_in[6];
    const float* UMAX = (const float*)d_in[7];
    const float* x0c  = (const float*)d_in[8];
    const float* UA   = (const float*)d_in[9];
    const float* sigA = (const float*)d_in[10];
    const float* VA   = (const float*)d_in[11];
    const float* UC   = (const float*)d_in[12];
    const float* sigC = (const float*)d_in[13];
    const float* VC   = (const float*)d_in[14];
    const float* wE   = (const float*)d_in[15];
    const float* sE   = (const float*)d_in[16];
    const float* wB   = (const float*)d_in[17];
    const float* Whf  = (const float*)d_in[18];
    const float* Wih  = (const float*)d_in[19];
    const float* Whh  = (const float*)d_in[20];
    const float* dxmn = (const float*)d_in[21];
    const float* dxmx = (const float*)d_in[22];
    float* out = (float*)d_out;

    static const size_t smem_pre = SM_PRE_FLOATS * sizeof(float);
    cudaFuncSetAttribute(k_pre, cudaFuncAttributeMaxDynamicSharedMemorySize,
                         (int)smem_pre);
    cudaFuncSetAttribute(k_c2, cudaFuncAttributeMaxDynamicSharedMemorySize,
                         SM_C2_BYTES);
    cudaFuncSetAttribute(k_post, cudaFuncAttributeMaxDynamicSharedMemorySize,
                         SM_POST_BYTES);

    float *Cg, *C2g, *WA2p, *T1p, *T2p, *WA128p;
    cudaGetSymbolAddress((void**)&Cg, g_C);
    cudaGetSymbolAddress((void**)&C2g, g_C2);
    cudaGetSymbolAddress((void**)&WA2p, g_WA2);
    cudaGetSymbolAddress((void**)&T1p, g_T1);
    cudaGetSymbolAddress((void**)&T2p, g_T2);
    cudaGetSymbolAddress((void**)&WA128p, g_WA128);

    k_setup<<<128, 128>>>(UA, sigA, VA, UC, sigC, VC);
    k_setup2<<<1, 128>>>(x0c, wE, sE, wB, out);
    k_wa2<<<128, 128>>>();
    k_pre<<<NSTEPSc, 512, smem_pre>>>(M, DTin, Din, UMIN, UMAX, Whf, dxmn, dxmx, out);
    k_matsq<<<128, 128>>>(WA2p, T1p);     // WA^4
    k_matsq<<<128, 128>>>(T1p, T2p);      // WA^8
    k_matsq<<<128, 128>>>(T2p, T1p);      // WA^16
    k_matsq<<<128, 128>>>(T1p, T2p);      // WA^32
    k_matsq<<<128, 128>>>(T2p, T1p);      // WA^64
    k_matsq<<<128, 128>>>(T1p, WA128p);   // WA^128
    k_rnn<<<Bc, 512>>>(Ym, Wih, Whh);
    k_c2<<<NSTEPSc, 256, SM_C2_BYTES>>>(Cg);
    k_scanlocal<<<(NSEG - 1) * 32, 256>>>(C2g);
    k_scanb<<<Bc, 128>>>();
    k_seqseg<<<NSEG * 32, 256>>>(XMIN, XMAX, Cg, out);
    k_post<<<(NSTEPSc * Bc) / 64, 256, SM_POST_BYTES>>>(out);
}